// round 10
// baseline (speedup 1.0000x reference)
#include <cuda_runtime.h>
#include <cuda_fp16.h>
#include <cstdint>
#include <cstddef>

#define BATCH   16384
#define HID     2048
#define NLAYER  8
#define PIN     25

#define MT      128
#define NT      128
#define KC      64                  // 64 fp16 k-values = 128B per row
#define NCH     (HID / KC)          // 32
#define NSTG    3
#define ABYTES  (MT * 128)          // 16384
#define BBYTES  (NT * 128)          // 16384
#define STGB    (ABYTES + BBYTES)   // 32768
#define DYNSMEM (NSTG * STGB + 1024) // 99328  (x2 CTAs = 194.5KB/SM)
#define NTHR    512                 // 16 warps -> 32 warps/SM at 2 CTAs

// ---------------- device scratch (allocation-free) ----------------
__device__ float  g_h0[(size_t)BATCH * HID];     // exact fp32 activations
__device__ float  g_h1[(size_t)BATCH * HID];
__device__ __half g_ta0[(size_t)BATCH * HID];    // fp16-rounded MMA copies
__device__ __half g_ta1[(size_t)BATCH * HID];
__device__ __half g_wt[(size_t)NLAYER * HID * HID];  // W^T fp16 [l][n][k]
__device__ float  g_patch[(size_t)BATCH * PIN];

// ---------------- helpers ----------------
__device__ __forceinline__ uint32_t smem_u32(const void* p) {
    uint32_t a;
    asm("{ .reg .u64 t; cvta.to.shared.u64 t, %1; cvt.u32.u64 %0, t; }" : "=r"(a) : "l"(p));
    return a;
}

__device__ __forceinline__ void cp_async16(uint32_t s, const void* g) {
    asm volatile("cp.async.cg.shared.global [%0], [%1], 16;" :: "r"(s), "l"(g) : "memory");
}

__device__ __forceinline__ void mma_f16(float* c, const uint32_t* a, const uint32_t* b) {
    asm volatile(
        "mma.sync.aligned.m16n8k16.row.col.f32.f16.f16.f32 "
        "{%0,%1,%2,%3}, {%4,%5,%6,%7}, {%8,%9}, {%0,%1,%2,%3};"
        : "+f"(c[0]), "+f"(c[1]), "+f"(c[2]), "+f"(c[3])
        : "r"(a[0]), "r"(a[1]), "r"(a[2]), "r"(a[3]), "r"(b[0]), "r"(b[1]));
}

#define LDSM4(r0, r1, r2, r3, addr) \
    asm volatile("ldmatrix.sync.aligned.m8n8.x4.shared.b16 {%0,%1,%2,%3}, [%4];" \
        : "=r"(r0), "=r"(r1), "=r"(r2), "=r"(r3) : "r"(addr))

// ============================================================
// Kernel 1: find agent, extract 5x5 patch (pad -1)
// ============================================================
__global__ void __launch_bounds__(256) patch_kernel(const float* __restrict__ x) {
    int w = threadIdx.x >> 5, lane = threadIdx.x & 31;
    int b = blockIdx.x * 8 + w;
    const float* xb = x + (size_t)b * 1024;
    int found = 0;
#pragma unroll
    for (int s = 0; s < 32; s++)
        if (xb[s * 32 + lane] == 3.0f) found = s * 32 + lane;
#pragma unroll
    for (int off = 16; off; off >>= 1)
        found = max(found, __shfl_xor_sync(0xffffffffu, found, off));
    int row = found >> 5, col = found & 31;
    if (lane < PIN) {
        int r = row + lane / 5 - 2;
        int c = col + lane % 5 - 2;
        float v = (r < 0 || r > 31 || c < 0 || c > 31) ? -1.0f : xb[r * 32 + c];
        g_patch[(size_t)b * PIN + lane] = v;
    }
}

// ============================================================
// Kernel 2: transpose W[l][k][n] -> g_wt[l][n][k] as fp16 (RN)
// ============================================================
__global__ void wtrans_kernel(const float* __restrict__ Wall) {
    __shared__ float t[32][33];
    const float* W = Wall + (size_t)blockIdx.z * HID * HID;
    __half* WT = g_wt + (size_t)blockIdx.z * HID * HID;
    int n0 = blockIdx.x * 32, k0 = blockIdx.y * 32;
    int tx = threadIdx.x, ty = threadIdx.y;
#pragma unroll
    for (int i = 0; i < 4; i++)
        t[ty + i * 8][tx] = W[(size_t)(k0 + ty + i * 8) * HID + n0 + tx];
    __syncthreads();
#pragma unroll
    for (int i = 0; i < 4; i++)
        WT[(size_t)(n0 + ty + i * 8) * HID + k0 + tx] = __float2half_rn(t[tx][ty + i * 8]);
}

// ============================================================
// Kernel 3: embed  h0 = patch . embed_W + embed_b  (K=25); writes fp32 + fp16
// ============================================================
__global__ void __launch_bounds__(256) embed_kernel(const float* __restrict__ eW,
                                                    const float* __restrict__ eb) {
    __shared__ float sp[64][PIN];
    int mb = blockIdx.y * 64, nb = blockIdx.x * 128;
    for (int i = threadIdx.x; i < 64 * PIN; i += 256)
        sp[i / PIN][i % PIN] = g_patch[(size_t)(mb + i / PIN) * PIN + i % PIN];
    __syncthreads();
    int col = threadIdx.x & 127, sg = threadIdx.x >> 7;
    float acc[32];
    float b = eb[nb + col];
#pragma unroll
    for (int s = 0; s < 32; s++) acc[s] = b;
    for (int k = 0; k < PIN; k++) {
        float w = eW[(size_t)k * HID + nb + col];
#pragma unroll
        for (int s = 0; s < 32; s++) acc[s] += sp[sg * 32 + s][k] * w;
    }
#pragma unroll
    for (int s = 0; s < 32; s++) {
        size_t idx = (size_t)(mb + sg * 32 + s) * HID + nb + col;
        g_h0[idx] = acc[s];
        g_ta0[idx] = __float2half_rn(acc[s]);
    }
}

// ============================================================
// Kernel 4: residual layer  C = A + relu(A @ W_l + b_l)
// mma.sync f16 m16n8k16, 128x128 CTA tile, 16 warps (4m x 4n) of 32x32,
// 3-stage cp.async pipeline, 97KB smem/CTA -> 2 CTAs/SM = 32 warps/SM
// (8 per SMSP). Small per-thread state (acc 32 regs) fits 64-reg cap.
// ============================================================
__global__ void __launch_bounds__(NTHR, 2) gemm_kernel(int l, int dir,
                                                       const float* __restrict__ bias) {
    const __half* __restrict__ Ah = dir ? g_ta1 : g_ta0;
    const __half* __restrict__ W  = g_wt + (size_t)l * HID * HID;

    extern __shared__ char dynsmem[];
    uint32_t raw = smem_u32(dynsmem);
    uint32_t sbase = (raw + 1023u) & ~1023u;

    __shared__ float sbias[NT];

    int tid = threadIdx.x;
    int mbase = blockIdx.y * MT, nbase = blockIdx.x * NT;
    if (tid < NT) sbias[tid] = bias[nbase + tid];

    int wid = tid >> 5, lane = tid & 31;
    int wm = wid & 3, wn = wid >> 2;          // 4 m-warps x 4 n-warps
    int g = lane >> 2, t = lane & 3;

    // ldmatrix lane decomposition
    int rl  = lane & 7;                       // row within 8x8 matrix
    int sec = lane >> 3;                      // which 8x8 matrix this lane addresses
    int hi_a = sec >> 1;                      // A: k-chunk select (matrices 2,3)
    int r8_a = sec & 1;                       // A: row+8 select   (matrices 1,3)
    int hi_b = sec & 1;                       // B: k-chunk select (matrices 1,3)
    int nfo_b = sec >> 1;                     // B: second n-fragment (matrices 2,3)

    uint32_t rowbase_a[2];
#pragma unroll
    for (int mf = 0; mf < 2; mf++)
        rowbase_a[mf] = (uint32_t)(wm * 32 + mf * 16 + r8_a * 8 + rl) * 128;
    uint32_t rowbase_b[2];
#pragma unroll
    for (int p = 0; p < 2; p++)
        rowbase_b[p] = (uint32_t)ABYTES
                     + (uint32_t)(wn * 32 + (2 * p + nfo_b) * 8 + rl) * 128;

    auto load_chunk = [&](int c) {
        uint32_t sa = sbase + (uint32_t)(c % NSTG) * STGB;
        uint32_t sb = sa + ABYTES;
        int kb = c * KC;
#pragma unroll
        for (int i = 0; i < 4; i++) {
            int idx = tid + i * NTHR;
            if (idx < 1024) {                 // A: 128 rows x 8 chunks of 8 fp16
                int r = idx >> 3, cid = idx & 7;
                cp_async16(sa + r * 128 + ((cid ^ (r & 7)) * 16),
                           Ah + (size_t)(mbase + r) * HID + kb + cid * 8);
            } else {                          // B: 128 rows x 8 chunks
                int j = idx - 1024;
                int r = j >> 3, cid = j & 7;
                cp_async16(sb + r * 128 + ((cid ^ (r & 7)) * 16),
                           W + (size_t)(nbase + r) * HID + kb + cid * 8);
            }
        }
    };

    float acc[2][4][4];
#pragma unroll
    for (int i = 0; i < 2; i++)
#pragma unroll
        for (int j = 0; j < 4; j++)
#pragma unroll
            for (int q = 0; q < 4; q++) acc[i][j][q] = 0.0f;

    // prologue: load chunks 0,1
    for (int c = 0; c < 2; c++) {
        load_chunk(c);
        asm volatile("cp.async.commit_group;" ::: "memory");
    }

    for (int c = 0; c < NCH; c++) {
        asm volatile("cp.async.wait_group 1;" ::: "memory");   // chunk c resident
        __syncthreads();                                        // stage (c+2)%3 free
        uint32_t stb = sbase + (uint32_t)(c % NSTG) * STGB;
        int nc = c + 2;
        if (nc < NCH) load_chunk(nc);
        asm volatile("cp.async.commit_group;" ::: "memory");

#pragma unroll
        for (int ks = 0; ks < 4; ks++) {
            uint32_t offa = (uint32_t)((((2 * ks) | hi_a) ^ rl) * 16);
            uint32_t offb = (uint32_t)((((2 * ks) | hi_b) ^ rl) * 16);
            uint32_t fa[2][4], fb[4][2];
#pragma unroll
            for (int mf = 0; mf < 2; mf++)
                LDSM4(fa[mf][0], fa[mf][1], fa[mf][2], fa[mf][3],
                      stb + rowbase_a[mf] + offa);
#pragma unroll
            for (int p = 0; p < 2; p++)
                LDSM4(fb[2 * p][0], fb[2 * p][1], fb[2 * p + 1][0], fb[2 * p + 1][1],
                      stb + rowbase_b[p] + offb);
#pragma unroll
            for (int mf = 0; mf < 2; mf++)
#pragma unroll
                for (int nf = 0; nf < 4; nf++)
                    mma_f16(acc[mf][nf], fa[mf], fb[nf]);
        }
    }
    asm volatile("cp.async.wait_group 0;" ::: "memory");

    // epilogue: bias + relu + residual (pointers recomputed here; cold regs)
    const float* Abase = dir ? g_h1 : g_h0;
    float*       Cbase = dir ? g_h0 : g_h1;
    __half*      Chb   = dir ? g_ta0 : g_ta1;
    int mb0 = mbase + wm * 32, nb0 = nbase + wn * 32;
#pragma unroll
    for (int mf = 0; mf < 2; mf++) {
#pragma unroll
        for (int half = 0; half < 2; half++) {
            int row = mb0 + mf * 16 + half * 8 + g;
            const float* Ar = Abase + (size_t)row * HID + nb0;
            float* Cr = Cbase + (size_t)row * HID + nb0;
            __half* Chr = Chb + (size_t)row * HID + nb0;
#pragma unroll
            for (int nf = 0; nf < 4; nf++) {
                int cl = nf * 8 + 2 * t;
                float2 res = *(const float2*)(Ar + cl);
                float b0 = sbias[wn * 32 + cl];
                float b1 = sbias[wn * 32 + cl + 1];
                float v0 = acc[mf][nf][half * 2 + 0];
                float v1 = acc[mf][nf][half * 2 + 1];
                float2 o;
                o.x = res.x + fmaxf(v0 + b0, 0.0f);
                o.y = res.y + fmaxf(v1 + b1, 0.0f);
                *(float2*)(Cr + cl) = o;
                *(__half2*)(Chr + cl) = __floats2half2_rn(o.x, o.y);
            }
        }
    }
}

// ============================================================
// Kernel 5: LayerNorm + head (N=4). One warp per row. Reads exact fp32.
// ============================================================
__global__ void __launch_bounds__(256) head_kernel(const float* __restrict__ lng,
                                                   const float* __restrict__ lnb,
                                                   const float* __restrict__ hW,
                                                   const float* __restrict__ hb,
                                                   float* __restrict__ out) {
    int w = threadIdx.x >> 5, lane = threadIdx.x & 31;
    int row = blockIdx.x * 8 + w;
    const float4* h4 = (const float4*)(g_h0 + (size_t)row * HID);
    float4 v[16];
    float s = 0.f, ss = 0.f;
#pragma unroll
    for (int i = 0; i < 16; i++) {
        v[i] = h4[i * 32 + lane];
        s += v[i].x + v[i].y + v[i].z + v[i].w;
        ss += v[i].x * v[i].x + v[i].y * v[i].y + v[i].z * v[i].z + v[i].w * v[i].w;
    }
#pragma unroll
    for (int off = 16; off; off >>= 1) {
        s += __shfl_xor_sync(0xffffffffu, s, off);
        ss += __shfl_xor_sync(0xffffffffu, ss, off);
    }
    float mu = s * (1.0f / HID);
    float var = ss * (1.0f / HID) - mu * mu;
    float rs = rsqrtf(var + 1e-5f);
    float a0 = 0.f, a1 = 0.f, a2 = 0.f, a3 = 0.f;
    const float4* g4 = (const float4*)lng;
    const float4* b4 = (const float4*)lnb;
    const float4* w4 = (const float4*)hW;
#pragma unroll 1
    for (int i = 0; i < 16; i++) {
        int k4 = i * 32 + lane;
        float4 gg = g4[k4], bb = b4[k4];
        float hn[4];
        hn[0] = (v[i].x - mu) * rs * gg.x + bb.x;
        hn[1] = (v[i].y - mu) * rs * gg.y + bb.y;
        hn[2] = (v[i].z - mu) * rs * gg.z + bb.z;
        hn[3] = (v[i].w - mu) * rs * gg.w + bb.w;
#pragma unroll
        for (int j = 0; j < 4; j++) {
            float4 wr = w4[k4 * 4 + j];
            a0 += hn[j] * wr.x;
            a1 += hn[j] * wr.y;
            a2 += hn[j] * wr.z;
            a3 += hn[j] * wr.w;
        }
    }
#pragma unroll
    for (int off = 16; off; off >>= 1) {
        a0 += __shfl_xor_sync(0xffffffffu, a0, off);
        a1 += __shfl_xor_sync(0xffffffffu, a1, off);
        a2 += __shfl_xor_sync(0xffffffffu, a2, off);
        a3 += __shfl_xor_sync(0xffffffffu, a3, off);
    }
    if (lane == 0) {
        float4 hbv = *(const float4*)hb;
        float4 o;
        o.x = a0 + hbv.x; o.y = a1 + hbv.y; o.z = a2 + hbv.z; o.w = a3 + hbv.w;
        ((float4*)out)[row] = o;
    }
}

// ============================================================
extern "C" void kernel_launch(void* const* d_in, const int* in_sizes, int n_in,
                              void* d_out, int out_size) {
    const float* x   = (const float*)d_in[0];
    const float* eW  = (const float*)d_in[1];
    const float* eb  = (const float*)d_in[2];
    const float* lW  = (const float*)d_in[3];
    const float* lb  = (const float*)d_in[4];
    const float* lng = (const float*)d_in[5];
    const float* lnb = (const float*)d_in[6];
    const float* hW  = (const float*)d_in[7];
    const float* hb  = (const float*)d_in[8];

    cudaFuncSetAttribute(gemm_kernel, cudaFuncAttributeMaxDynamicSharedMemorySize, DYNSMEM);

    patch_kernel<<<BATCH / 8, 256>>>(x);
    wtrans_kernel<<<dim3(HID / 32, HID / 32, NLAYER), dim3(32, 8)>>>(lW);
    embed_kernel<<<dim3(HID / 128, BATCH / 64), 256>>>(eW, eb);
    for (int l = 0; l < NLAYER; l++)
        gemm_kernel<<<dim3(HID / NT, BATCH / MT), NTHR, DYNSMEM>>>(l, l & 1, lb + (size_t)l * HID);
    head_kernel<<<BATCH / 8, 256>>>(lng, lnb, hW, hb, (float*)d_out);
}

// round 11
// speedup vs baseline: 1.2537x; 1.2537x over previous
#include <cuda_runtime.h>
#include <cuda_fp16.h>
#include <cstdint>
#include <cstddef>

#define BATCH   16384
#define HID     2048
#define NLAYER  8
#define PIN     25

#define MT      128
#define NT      128
#define KC      64                  // 64 fp16 k-values = 128B per row
#define NCH     (HID / KC)          // 32
#define NSTG    3
#define ABYTES  (MT * 128)          // 16384
#define BBYTES  (NT * 128)          // 16384
#define STGB    (ABYTES + BBYTES)   // 32768
#define DYNSMEM (NSTG * STGB + 1024) // 99328  (x2 CTAs = 194.5KB/SM)
#define NTHR    256

// ---------------- device scratch (allocation-free) ----------------
__device__ float  g_h0[(size_t)BATCH * HID];     // exact fp32 activations
__device__ float  g_h1[(size_t)BATCH * HID];
__device__ __half g_ta0[(size_t)BATCH * HID];    // fp16-rounded MMA copies
__device__ __half g_ta1[(size_t)BATCH * HID];
__device__ __half g_wt[(size_t)NLAYER * HID * HID];  // W^T fp16 [l][n][k]
__device__ float  g_patch[(size_t)BATCH * PIN];

// ---------------- helpers ----------------
__device__ __forceinline__ uint32_t smem_u32(const void* p) {
    uint32_t a;
    asm("{ .reg .u64 t; cvta.to.shared.u64 t, %1; cvt.u32.u64 %0, t; }" : "=r"(a) : "l"(p));
    return a;
}

__device__ __forceinline__ void cp_async16(uint32_t s, const void* g) {
    asm volatile("cp.async.cg.shared.global [%0], [%1], 16;" :: "r"(s), "l"(g) : "memory");
}

__device__ __forceinline__ void mma_f16(float* c, const uint32_t* a, const uint32_t* b) {
    asm volatile(
        "mma.sync.aligned.m16n8k16.row.col.f32.f16.f16.f32 "
        "{%0,%1,%2,%3}, {%4,%5,%6,%7}, {%8,%9}, {%0,%1,%2,%3};"
        : "+f"(c[0]), "+f"(c[1]), "+f"(c[2]), "+f"(c[3])
        : "r"(a[0]), "r"(a[1]), "r"(a[2]), "r"(a[3]), "r"(b[0]), "r"(b[1]));
}

#define LDSM4(r0, r1, r2, r3, addr) \
    asm volatile("ldmatrix.sync.aligned.m8n8.x4.shared.b16 {%0,%1,%2,%3}, [%4];" \
        : "=r"(r0), "=r"(r1), "=r"(r2), "=r"(r3) : "r"(addr))

#define MBARRIER_INIT(addr, count) \
    asm volatile("mbarrier.init.shared.b64 [%0], %1;" \
        :: "r"((uint32_t)(addr)), "r"((uint32_t)(count)) : "memory")

#define MBARRIER_ARRIVE(addr) \
    asm volatile("mbarrier.arrive.shared.b64 _, [%0];" \
        :: "r"((uint32_t)(addr)) : "memory")

#define CPASYNC_MBAR_ARRIVE(addr) \
    asm volatile("cp.async.mbarrier.arrive.noinc.shared.b64 [%0];" \
        :: "r"((uint32_t)(addr)) : "memory")

#define MBARRIER_WAIT_PARITY(mbar_smem_addr, phase_parity) do { \
    uint32_t _mbar = (uint32_t)(mbar_smem_addr); \
    uint32_t _parity = (uint32_t)(phase_parity); \
    uint32_t _done; \
    asm volatile( \
        "{\n\t.reg .pred p;\n\t" \
        "mbarrier.try_wait.parity.acquire.cta.shared::cta.b64 p, [%1], %2;\n\t" \
        "selp.b32 %0, 1, 0, p;\n\t}" \
        : "=r"(_done) : "r"(_mbar), "r"(_parity) : "memory"); \
    if (!_done) { \
        asm volatile( \
            "{\n\t.reg .pred P1;\n\t" \
            "WAIT_LOOP_%=:\n\t" \
            "mbarrier.try_wait.parity.acquire.cta.shared::cta.b64 P1, [%0], %1, 0x989680;\n\t" \
            "@P1 bra.uni WAIT_DONE_%=;\n\t" \
            "bra.uni WAIT_LOOP_%=;\n\t" \
            "WAIT_DONE_%=:\n\t}" \
            :: "r"(_mbar), "r"(_parity) : "memory"); \
    } \
} while (0)

// ============================================================
// Kernel 1: find agent, extract 5x5 patch (pad -1)
// ============================================================
__global__ void __launch_bounds__(256) patch_kernel(const float* __restrict__ x) {
    int w = threadIdx.x >> 5, lane = threadIdx.x & 31;
    int b = blockIdx.x * 8 + w;
    const float* xb = x + (size_t)b * 1024;
    int found = 0;
#pragma unroll
    for (int s = 0; s < 32; s++)
        if (xb[s * 32 + lane] == 3.0f) found = s * 32 + lane;
#pragma unroll
    for (int off = 16; off; off >>= 1)
        found = max(found, __shfl_xor_sync(0xffffffffu, found, off));
    int row = found >> 5, col = found & 31;
    if (lane < PIN) {
        int r = row + lane / 5 - 2;
        int c = col + lane % 5 - 2;
        float v = (r < 0 || r > 31 || c < 0 || c > 31) ? -1.0f : xb[r * 32 + c];
        g_patch[(size_t)b * PIN + lane] = v;
    }
}

// ============================================================
// Kernel 2: transpose W[l][k][n] -> g_wt[l][n][k] as fp16 (RN)
// ============================================================
__global__ void wtrans_kernel(const float* __restrict__ Wall) {
    __shared__ float t[32][33];
    const float* W = Wall + (size_t)blockIdx.z * HID * HID;
    __half* WT = g_wt + (size_t)blockIdx.z * HID * HID;
    int n0 = blockIdx.x * 32, k0 = blockIdx.y * 32;
    int tx = threadIdx.x, ty = threadIdx.y;
#pragma unroll
    for (int i = 0; i < 4; i++)
        t[ty + i * 8][tx] = W[(size_t)(k0 + ty + i * 8) * HID + n0 + tx];
    __syncthreads();
#pragma unroll
    for (int i = 0; i < 4; i++)
        WT[(size_t)(n0 + ty + i * 8) * HID + k0 + tx] = __float2half_rn(t[tx][ty + i * 8]);
}

// ============================================================
// Kernel 3: embed  h0 = patch . embed_W + embed_b  (K=25); writes fp32 + fp16
// ============================================================
__global__ void __launch_bounds__(256) embed_kernel(const float* __restrict__ eW,
                                                    const float* __restrict__ eb) {
    __shared__ float sp[64][PIN];
    int mb = blockIdx.y * 64, nb = blockIdx.x * 128;
    for (int i = threadIdx.x; i < 64 * PIN; i += 256)
        sp[i / PIN][i % PIN] = g_patch[(size_t)(mb + i / PIN) * PIN + i % PIN];
    __syncthreads();
    int col = threadIdx.x & 127, sg = threadIdx.x >> 7;
    float acc[32];
    float b = eb[nb + col];
#pragma unroll
    for (int s = 0; s < 32; s++) acc[s] = b;
    for (int k = 0; k < PIN; k++) {
        float w = eW[(size_t)k * HID + nb + col];
#pragma unroll
        for (int s = 0; s < 32; s++) acc[s] += sp[sg * 32 + s][k] * w;
    }
#pragma unroll
    for (int s = 0; s < 32; s++) {
        size_t idx = (size_t)(mb + sg * 32 + s) * HID + nb + col;
        g_h0[idx] = acc[s];
        g_ta0[idx] = __float2half_rn(acc[s]);
    }
}

// ============================================================
// Kernel 4: residual layer  C = A + relu(A @ W_l + b_l)
// mma.sync f16 m16n8k16, 128x128 CTA tile, 8 warps (2m x 4n) of 64x32,
// 3-stage ring, 2 CTAs/SM. Mainloop sync is per-stage mbarrier pairs
// (full: cp.async completion tracking; free: one arrive per consumer warp)
// -- NO __syncthreads in the loop, warps run desynchronized within the
// 2-chunk ring slack so chunk-boundary convergence stalls vanish.
// ============================================================
__global__ void __launch_bounds__(NTHR, 2) gemm_kernel(int l, int dir,
                                                       const float* __restrict__ bias) {
    const __half* __restrict__ Ah = dir ? g_ta1 : g_ta0;
    const __half* __restrict__ W  = g_wt + (size_t)l * HID * HID;

    extern __shared__ char dynsmem[];
    uint32_t raw = smem_u32(dynsmem);
    uint32_t sbase = (raw + 1023u) & ~1023u;

    __shared__ float sbias[NT];
    __shared__ __align__(8) unsigned long long mbars[2 * NSTG];  // full[0..2], free[0..2]

    int tid = threadIdx.x;
    int mbase = blockIdx.y * MT, nbase = blockIdx.x * NT;
    if (tid < NT) sbias[tid] = bias[nbase + tid];

    uint32_t mb_full = smem_u32(&mbars[0]);
    uint32_t mb_free = smem_u32(&mbars[NSTG]);
    if (tid == 0) {
#pragma unroll
        for (int s = 0; s < NSTG; s++) {
            MBARRIER_INIT(mb_full + s * 8, NTHR);  // all threads' cp.async completions
            MBARRIER_INIT(mb_free + s * 8, 8);     // one arrive per consumer warp
        }
    }
    __syncthreads();   // mbars + sbias visible; only barrier in the kernel

    int wid = tid >> 5, lane = tid & 31;
    int wm = wid & 1, wn = wid >> 1;          // 2 m-warps x 4 n-warps
    int g = lane >> 2, t = lane & 3;

    // ldmatrix lane decomposition
    int rl  = lane & 7;
    int sec = lane >> 3;
    int hi_a = sec >> 1;
    int r8_a = sec & 1;
    int hi_b = sec & 1;
    int nfo_b = sec >> 1;

    uint32_t rowbase_a[4];
#pragma unroll
    for (int mf = 0; mf < 4; mf++)
        rowbase_a[mf] = (uint32_t)(wm * 64 + mf * 16 + r8_a * 8 + rl) * 128;
    uint32_t rowbase_b[2];
#pragma unroll
    for (int p = 0; p < 2; p++)
        rowbase_b[p] = (uint32_t)ABYTES
                     + (uint32_t)(wn * 32 + (2 * p + nfo_b) * 8 + rl) * 128;

    auto load_chunk = [&](int c) {
        uint32_t sa = sbase + (uint32_t)(c % NSTG) * STGB;
        uint32_t sb = sa + ABYTES;
        int kb = c * KC;
#pragma unroll
        for (int i = 0; i < 8; i++) {
            int idx = tid + i * NTHR;
            if (idx < 1024) {                 // A: 128 rows x 8 chunks of 8 fp16
                int r = idx >> 3, cid = idx & 7;
                cp_async16(sa + r * 128 + ((cid ^ (r & 7)) * 16),
                           Ah + (size_t)(mbase + r) * HID + kb + cid * 8);
            } else {                          // B: 128 rows x 8 chunks
                int j = idx - 1024;
                int r = j >> 3, cid = j & 7;
                cp_async16(sb + r * 128 + ((cid ^ (r & 7)) * 16),
                           W + (size_t)(nbase + r) * HID + kb + cid * 8);
            }
        }
    };

    float acc[4][4][4];
#pragma unroll
    for (int i = 0; i < 4; i++)
#pragma unroll
        for (int j = 0; j < 4; j++)
#pragma unroll
            for (int q = 0; q < 4; q++) acc[i][j][q] = 0.0f;

    // prologue: load chunks 0,1 (stages 0,1 start free)
    load_chunk(0);
    CPASYNC_MBAR_ARRIVE(mb_full + 0 * 8);
    load_chunk(1);
    CPASYNC_MBAR_ARRIVE(mb_full + 1 * 8);

    for (int c = 0; c < NCH; c++) {
        int s = c % NSTG;
        uint32_t stb = sbase + (uint32_t)s * STGB;

        // consumer: wait chunk c's loads complete (acquire)
        MBARRIER_WAIT_PARITY(mb_full + s * 8, (c / NSTG) & 1);

#pragma unroll
        for (int ks = 0; ks < 4; ks++) {
            uint32_t offa = (uint32_t)((((2 * ks) | hi_a) ^ rl) * 16);
            uint32_t offb = (uint32_t)((((2 * ks) | hi_b) ^ rl) * 16);
            uint32_t fa[4][4], fb[4][2];
#pragma unroll
            for (int mf = 0; mf < 4; mf++)
                LDSM4(fa[mf][0], fa[mf][1], fa[mf][2], fa[mf][3],
                      stb + rowbase_a[mf] + offa);
#pragma unroll
            for (int p = 0; p < 2; p++)
                LDSM4(fb[2 * p][0], fb[2 * p][1], fb[2 * p + 1][0], fb[2 * p + 1][1],
                      stb + rowbase_b[p] + offb);
#pragma unroll
            for (int mf = 0; mf < 4; mf++)
#pragma unroll
                for (int nf = 0; nf < 4; nf++)
                    mma_f16(acc[mf][nf], fa[mf], fb[nf]);
        }
        // this warp is done reading stage s (ldmatrix is warp-synchronous)
        if (lane == 0) MBARRIER_ARRIVE(mb_free + s * 8);

        // producer: refill stage (c+2)%3 with chunk c+2
        int nc = c + 2;
        if (nc < NCH) {
            int s2 = nc % NSTG;
            if (nc >= NSTG)   // wait until all warps finished reading chunk nc-3
                MBARRIER_WAIT_PARITY(mb_free + s2 * 8, ((nc - NSTG) / NSTG) & 1);
            load_chunk(nc);
            CPASYNC_MBAR_ARRIVE(mb_full + s2 * 8);
        }
    }

    // epilogue: bias + relu + residual (pointers recomputed here; cold regs)
    const float* Abase = dir ? g_h1 : g_h0;
    float*       Cbase = dir ? g_h0 : g_h1;
    __half*      Chb   = dir ? g_ta0 : g_ta1;
    int mb0 = mbase + wm * 64, nb0 = nbase + wn * 32;
#pragma unroll
    for (int mf = 0; mf < 4; mf++) {
#pragma unroll
        for (int half = 0; half < 2; half++) {
            int row = mb0 + mf * 16 + half * 8 + g;
            const float* Ar = Abase + (size_t)row * HID + nb0;
            float* Cr = Cbase + (size_t)row * HID + nb0;
            __half* Chr = Chb + (size_t)row * HID + nb0;
#pragma unroll
            for (int nf = 0; nf < 4; nf++) {
                int cl = nf * 8 + 2 * t;
                float2 res = *(const float2*)(Ar + cl);
                float b0 = sbias[wn * 32 + cl];
                float b1 = sbias[wn * 32 + cl + 1];
                float v0 = acc[mf][nf][half * 2 + 0];
                float v1 = acc[mf][nf][half * 2 + 1];
                float2 o;
                o.x = res.x + fmaxf(v0 + b0, 0.0f);
                o.y = res.y + fmaxf(v1 + b1, 0.0f);
                *(float2*)(Cr + cl) = o;
                *(__half2*)(Chr + cl) = __floats2half2_rn(o.x, o.y);
            }
        }
    }
}

// ============================================================
// Kernel 5: LayerNorm + head (N=4). One warp per row. Reads exact fp32.
// ============================================================
__global__ void __launch_bounds__(256) head_kernel(const float* __restrict__ lng,
                                                   const float* __restrict__ lnb,
                                                   const float* __restrict__ hW,
                                                   const float* __restrict__ hb,
                                                   float* __restrict__ out) {
    int w = threadIdx.x >> 5, lane = threadIdx.x & 31;
    int row = blockIdx.x * 8 + w;
    const float4* h4 = (const float4*)(g_h0 + (size_t)row * HID);
    float4 v[16];
    float s = 0.f, ss = 0.f;
#pragma unroll
    for (int i = 0; i < 16; i++) {
        v[i] = h4[i * 32 + lane];
        s += v[i].x + v[i].y + v[i].z + v[i].w;
        ss += v[i].x * v[i].x + v[i].y * v[i].y + v[i].z * v[i].z + v[i].w * v[i].w;
    }
#pragma unroll
    for (int off = 16; off; off >>= 1) {
        s += __shfl_xor_sync(0xffffffffu, s, off);
        ss += __shfl_xor_sync(0xffffffffu, ss, off);
    }
    float mu = s * (1.0f / HID);
    float var = ss * (1.0f / HID) - mu * mu;
    float rs = rsqrtf(var + 1e-5f);
    float a0 = 0.f, a1 = 0.f, a2 = 0.f, a3 = 0.f;
    const float4* g4 = (const float4*)lng;
    const float4* b4 = (const float4*)lnb;
    const float4* w4 = (const float4*)hW;
#pragma unroll 1
    for (int i = 0; i < 16; i++) {
        int k4 = i * 32 + lane;
        float4 gg = g4[k4], bb = b4[k4];
        float hn[4];
        hn[0] = (v[i].x - mu) * rs * gg.x + bb.x;
        hn[1] = (v[i].y - mu) * rs * gg.y + bb.y;
        hn[2] = (v[i].z - mu) * rs * gg.z + bb.z;
        hn[3] = (v[i].w - mu) * rs * gg.w + bb.w;
#pragma unroll
        for (int j = 0; j < 4; j++) {
            float4 wr = w4[k4 * 4 + j];
            a0 += hn[j] * wr.x;
            a1 += hn[j] * wr.y;
            a2 += hn[j] * wr.z;
            a3 += hn[j] * wr.w;
        }
    }
#pragma unroll
    for (int off = 16; off; off >>= 1) {
        a0 += __shfl_xor_sync(0xffffffffu, a0, off);
        a1 += __shfl_xor_sync(0xffffffffu, a1, off);
        a2 += __shfl_xor_sync(0xffffffffu, a2, off);
        a3 += __shfl_xor_sync(0xffffffffu, a3, off);
    }
    if (lane == 0) {
        float4 hbv = *(const float4*)hb;
        float4 o;
        o.x = a0 + hbv.x; o.y = a1 + hbv.y; o.z = a2 + hbv.z; o.w = a3 + hbv.w;
        ((float4*)out)[row] = o;
    }
}

// ============================================================
extern "C" void kernel_launch(void* const* d_in, const int* in_sizes, int n_in,
                              void* d_out, int out_size) {
    const float* x   = (const float*)d_in[0];
    const float* eW  = (const float*)d_in[1];
    const float* eb  = (const float*)d_in[2];
    const float* lW  = (const float*)d_in[3];
    const float* lb  = (const float*)d_in[4];
    const float* lng = (const float*)d_in[5];
    const float* lnb = (const float*)d_in[6];
    const float* hW  = (const float*)d_in[7];
    const float* hb  = (const float*)d_in[8];

    cudaFuncSetAttribute(gemm_kernel, cudaFuncAttributeMaxDynamicSharedMemorySize, DYNSMEM);

    patch_kernel<<<BATCH / 8, 256>>>(x);
    wtrans_kernel<<<dim3(HID / 32, HID / 32, NLAYER), dim3(32, 8)>>>(lW);
    embed_kernel<<<dim3(HID / 128, BATCH / 64), 256>>>(eW, eb);
    for (int l = 0; l < NLAYER; l++)
        gemm_kernel<<<dim3(HID / NT, BATCH / MT), NTHR, DYNSMEM>>>(l, l & 1, lb + (size_t)l * HID);
    head_kernel<<<BATCH / 8, 256>>>(lng, lnb, hW, hb, (float*)d_out);
}

// round 12
// speedup vs baseline: 1.2639x; 1.0081x over previous
#include <cuda_runtime.h>
#include <cuda_fp16.h>
#include <cstdint>
#include <cstddef>

#define BATCH   16384
#define HID     2048
#define NLAYER  8
#define PIN     25

#define MT      128
#define NT      128
#define KC      64                  // 64 fp16 k-values = 128B per row
#define NCH     (HID / KC)          // 32
#define NSTG    3
#define ABYTES  (MT * 128)          // 16384
#define BBYTES  (NT * 128)          // 16384
#define STGB    (ABYTES + BBYTES)   // 32768
#define DYNSMEM (NSTG * STGB + 1024) // 99328  (x2 CTAs = 194.5KB/SM)
#define NTHR    256

// ---------------- device scratch (allocation-free) ----------------
__device__ float  g_h0[(size_t)BATCH * HID];     // exact fp32 activations
__device__ float  g_h1[(size_t)BATCH * HID];
__device__ __half g_ta0[(size_t)BATCH * HID];    // fp16-rounded MMA copies
__device__ __half g_ta1[(size_t)BATCH * HID];
__device__ __half g_wt[(size_t)NLAYER * HID * HID];  // W^T fp16 [l][n][k]
__device__ float  g_patch[(size_t)BATCH * PIN];

// ---------------- helpers ----------------
__device__ __forceinline__ uint32_t smem_u32(const void* p) {
    uint32_t a;
    asm("{ .reg .u64 t; cvta.to.shared.u64 t, %1; cvt.u32.u64 %0, t; }" : "=r"(a) : "l"(p));
    return a;
}

__device__ __forceinline__ void cp_async16(uint32_t s, const void* g) {
    asm volatile("cp.async.cg.shared.global [%0], [%1], 16;" :: "r"(s), "l"(g) : "memory");
}

__device__ __forceinline__ void mma_f16(float* c, const uint32_t* a, const uint32_t* b) {
    asm volatile(
        "mma.sync.aligned.m16n8k16.row.col.f32.f16.f16.f32 "
        "{%0,%1,%2,%3}, {%4,%5,%6,%7}, {%8,%9}, {%0,%1,%2,%3};"
        : "+f"(c[0]), "+f"(c[1]), "+f"(c[2]), "+f"(c[3])
        : "r"(a[0]), "r"(a[1]), "r"(a[2]), "r"(a[3]), "r"(b[0]), "r"(b[1]));
}

#define LDSM4(r0, r1, r2, r3, addr) \
    asm volatile("ldmatrix.sync.aligned.m8n8.x4.shared.b16 {%0,%1,%2,%3}, [%4];" \
        : "=r"(r0), "=r"(r1), "=r"(r2), "=r"(r3) : "r"(addr))

#define MBARRIER_INIT(addr, count) \
    asm volatile("mbarrier.init.shared.b64 [%0], %1;" \
        :: "r"((uint32_t)(addr)), "r"((uint32_t)(count)) : "memory")

#define MBARRIER_ARRIVE(addr) \
    asm volatile("mbarrier.arrive.shared.b64 _, [%0];" \
        :: "r"((uint32_t)(addr)) : "memory")

#define CPASYNC_MBAR_ARRIVE(addr) \
    asm volatile("cp.async.mbarrier.arrive.noinc.shared.b64 [%0];" \
        :: "r"((uint32_t)(addr)) : "memory")

#define MBARRIER_WAIT_PARITY(mbar_smem_addr, phase_parity) do { \
    uint32_t _mbar = (uint32_t)(mbar_smem_addr); \
    uint32_t _parity = (uint32_t)(phase_parity); \
    uint32_t _done; \
    asm volatile( \
        "{\n\t.reg .pred p;\n\t" \
        "mbarrier.try_wait.parity.acquire.cta.shared::cta.b64 p, [%1], %2;\n\t" \
        "selp.b32 %0, 1, 0, p;\n\t}" \
        : "=r"(_done) : "r"(_mbar), "r"(_parity) : "memory"); \
    if (!_done) { \
        asm volatile( \
            "{\n\t.reg .pred P1;\n\t" \
            "WAIT_LOOP_%=:\n\t" \
            "mbarrier.try_wait.parity.acquire.cta.shared::cta.b64 P1, [%0], %1, 0x989680;\n\t" \
            "@P1 bra.uni WAIT_DONE_%=;\n\t" \
            "bra.uni WAIT_LOOP_%=;\n\t" \
            "WAIT_DONE_%=:\n\t}" \
            :: "r"(_mbar), "r"(_parity) : "memory"); \
    } \
} while (0)

// ============================================================
// Kernel 1: find agent, extract 5x5 patch (pad -1)
// ============================================================
__global__ void __launch_bounds__(256) patch_kernel(const float* __restrict__ x) {
    int w = threadIdx.x >> 5, lane = threadIdx.x & 31;
    int b = blockIdx.x * 8 + w;
    const float* xb = x + (size_t)b * 1024;
    int found = 0;
#pragma unroll
    for (int s = 0; s < 32; s++)
        if (xb[s * 32 + lane] == 3.0f) found = s * 32 + lane;
#pragma unroll
    for (int off = 16; off; off >>= 1)
        found = max(found, __shfl_xor_sync(0xffffffffu, found, off));
    int row = found >> 5, col = found & 31;
    if (lane < PIN) {
        int r = row + lane / 5 - 2;
        int c = col + lane % 5 - 2;
        float v = (r < 0 || r > 31 || c < 0 || c > 31) ? -1.0f : xb[r * 32 + c];
        g_patch[(size_t)b * PIN + lane] = v;
    }
}

// ============================================================
// Kernel 2: transpose W[l][k][n] -> g_wt[l][n][k] as fp16 (RN)
// ============================================================
__global__ void wtrans_kernel(const float* __restrict__ Wall) {
    __shared__ float t[32][33];
    const float* W = Wall + (size_t)blockIdx.z * HID * HID;
    __half* WT = g_wt + (size_t)blockIdx.z * HID * HID;
    int n0 = blockIdx.x * 32, k0 = blockIdx.y * 32;
    int tx = threadIdx.x, ty = threadIdx.y;
#pragma unroll
    for (int i = 0; i < 4; i++)
        t[ty + i * 8][tx] = W[(size_t)(k0 + ty + i * 8) * HID + n0 + tx];
    __syncthreads();
#pragma unroll
    for (int i = 0; i < 4; i++)
        WT[(size_t)(n0 + ty + i * 8) * HID + k0 + tx] = __float2half_rn(t[tx][ty + i * 8]);
}

// ============================================================
// Kernel 3: embed  h0 = patch . embed_W + embed_b  (K=25); writes fp32 + fp16
// ============================================================
__global__ void __launch_bounds__(256) embed_kernel(const float* __restrict__ eW,
                                                    const float* __restrict__ eb) {
    __shared__ float sp[64][PIN];
    int mb = blockIdx.y * 64, nb = blockIdx.x * 128;
    for (int i = threadIdx.x; i < 64 * PIN; i += 256)
        sp[i / PIN][i % PIN] = g_patch[(size_t)(mb + i / PIN) * PIN + i % PIN];
    __syncthreads();
    int col = threadIdx.x & 127, sg = threadIdx.x >> 7;
    float acc[32];
    float b = eb[nb + col];
#pragma unroll
    for (int s = 0; s < 32; s++) acc[s] = b;
    for (int k = 0; k < PIN; k++) {
        float w = eW[(size_t)k * HID + nb + col];
#pragma unroll
        for (int s = 0; s < 32; s++) acc[s] += sp[sg * 32 + s][k] * w;
    }
#pragma unroll
    for (int s = 0; s < 32; s++) {
        size_t idx = (size_t)(mb + sg * 32 + s) * HID + nb + col;
        g_h0[idx] = acc[s];
        g_ta0[idx] = __float2half_rn(acc[s]);
    }
}

// ============================================================
// Kernel 4: residual layer  C = A + relu(A @ W_l + b_l)
// mma.sync f16 m16n8k16, 128x128 CTA tile, 8 warps (2m x 4n) of 64x32,
// 3-stage mbarrier ring, 2 CTAs/SM. Fragment loads run as a stepped
// (ks,mf) pipeline: each of 16 steps issues 1 LDSM prefetch + 4 MMAs,
// fa in a 2-slot ring, fb double-buffered per ks; next chunk's first
// fragments prefetch during ks3. Strength-reduced cp.async addressing.
// ============================================================
__global__ void __launch_bounds__(NTHR, 2) gemm_kernel(int l, int dir,
                                                       const float* __restrict__ bias) {
    const __half* __restrict__ Ah = dir ? g_ta1 : g_ta0;
    const __half* __restrict__ W  = g_wt + (size_t)l * HID * HID;

    extern __shared__ char dynsmem[];
    uint32_t raw = smem_u32(dynsmem);
    uint32_t sbase = (raw + 1023u) & ~1023u;

    __shared__ float sbias[NT];
    __shared__ __align__(8) unsigned long long mbars[2 * NSTG];  // full[0..2], free[0..2]

    int tid = threadIdx.x;
    int mbase = blockIdx.y * MT, nbase = blockIdx.x * NT;
    if (tid < NT) sbias[tid] = bias[nbase + tid];

    uint32_t mb_full = smem_u32(&mbars[0]);
    uint32_t mb_free = smem_u32(&mbars[NSTG]);
    if (tid == 0) {
#pragma unroll
        for (int s = 0; s < NSTG; s++) {
            MBARRIER_INIT(mb_full + s * 8, NTHR);  // all threads' cp.async completions
            MBARRIER_INIT(mb_free + s * 8, 8);     // one arrive per consumer warp
        }
    }
    __syncthreads();   // mbars + sbias visible; only __syncthreads in the kernel

    int wid = tid >> 5, lane = tid & 31;
    int wm = wid & 1, wn = wid >> 1;          // 2 m-warps x 4 n-warps
    int g = lane >> 2, t = lane & 3;

    // ldmatrix lane decomposition
    int rl  = lane & 7;
    int sec = lane >> 3;
    int hi_a = sec >> 1;
    int r8_a = sec & 1;
    int hi_b = sec & 1;
    int nfo_b = sec >> 1;

    uint32_t rowbase_a[4];
#pragma unroll
    for (int mf = 0; mf < 4; mf++)
        rowbase_a[mf] = (uint32_t)(wm * 64 + mf * 16 + r8_a * 8 + rl) * 128;
    uint32_t rowbase_b[2];
#pragma unroll
    for (int p = 0; p < 2; p++)
        rowbase_b[p] = (uint32_t)ABYTES
                     + (uint32_t)(wn * 32 + (2 * p + nfo_b) * 8 + rl) * 128;

    // strength-reduced loader state: per-thread invariant smem offset + global base
    int lrow = tid >> 3, lcid = tid & 7;
    uint32_t aSmOff = (uint32_t)(lrow * 128 + ((lcid ^ (lrow & 7)) * 16));
    uint32_t bSmOff = (uint32_t)ABYTES + aSmOff;   // same row/swizzle pattern
    const __half* aG = Ah + (size_t)(mbase + lrow) * HID + lcid * 8;
    const __half* bG = W  + (size_t)(nbase + lrow) * HID + lcid * 8;

    auto load_chunk = [&](int c) {
        uint32_t sa = sbase + (uint32_t)(c % NSTG) * STGB;
        const __half* a = aG + c * KC;
        const __half* b = bG + c * KC;
#pragma unroll
        for (int i = 0; i < 4; i++) {
            cp_async16(sa + aSmOff + i * 4096, a + (size_t)i * 32 * HID);
            cp_async16(sa + bSmOff + i * 4096, b + (size_t)i * 32 * HID);
        }
    };

    float acc[4][4][4];
#pragma unroll
    for (int i = 0; i < 4; i++)
#pragma unroll
        for (int j = 0; j < 4; j++)
#pragma unroll
            for (int q = 0; q < 4; q++) acc[i][j][q] = 0.0f;

    uint32_t fa[2][4];   // 2-slot fa ring (one 16x16 m-fragment per slot)
    uint32_t fb[2][8];   // per-ks double-buffered B fragments (4 n-frags)

    auto ldfa = [&](uint32_t stb, int ks, int mf, int slot) {
        uint32_t offa = (uint32_t)((((2 * ks) | hi_a) ^ rl) * 16);
        LDSM4(fa[slot][0], fa[slot][1], fa[slot][2], fa[slot][3],
              stb + rowbase_a[mf] + offa);
    };
    auto ldfb = [&](uint32_t stb, int ks, int slot) {
        uint32_t offb = (uint32_t)((((2 * ks) | hi_b) ^ rl) * 16);
        LDSM4(fb[slot][0], fb[slot][1], fb[slot][2], fb[slot][3],
              stb + rowbase_b[0] + offb);
        LDSM4(fb[slot][4], fb[slot][5], fb[slot][6], fb[slot][7],
              stb + rowbase_b[1] + offb);
    };

    // prologue: load chunks 0,1; preload chunk 0's first fragments
    load_chunk(0);
    CPASYNC_MBAR_ARRIVE(mb_full + 0 * 8);
    load_chunk(1);
    CPASYNC_MBAR_ARRIVE(mb_full + 1 * 8);
    MBARRIER_WAIT_PARITY(mb_full + 0 * 8, 0);
    ldfa(sbase, 0, 0, 0);
    ldfb(sbase, 0, 0);

    for (int c = 0; c < NCH; c++) {
        int s = c % NSTG;
        uint32_t stb = sbase + (uint32_t)s * STGB;
        int s1 = (c + 1) % NSTG;
        uint32_t stb1 = sbase + (uint32_t)s1 * STGB;
        int p1 = ((c + 1) / NSTG) & 1;
        bool more = (c + 1 < NCH);

#pragma unroll
        for (int ks = 0; ks < 4; ks++) {
            int fbc = ks & 1;
            if (ks == 3 && more)
                MBARRIER_WAIT_PARITY(mb_full + s1 * 8, p1);   // chunk c+1 data ready
#pragma unroll
            for (int mf = 0; mf < 4; mf++) {
                int step = ks * 4 + mf;
                int p = step & 1;
                if (mf == 2) {                  // prefetch next ks's B fragments
                    if (ks < 3) ldfb(stb, ks + 1, fbc ^ 1);
                    else if (more) ldfb(stb1, 0, 0);
                }
                if (step < 15)                  // prefetch next step's A fragment
                    ldfa(stb, (step + 1) >> 2, (step + 1) & 3, p ^ 1);
                else if (more)
                    ldfa(stb1, 0, 0, 0);
#pragma unroll
                for (int nf = 0; nf < 4; nf++)
                    mma_f16(acc[mf][nf], fa[p], &fb[fbc][nf * 2]);
            }
        }
        // this warp is done reading stage s
        if (lane == 0) MBARRIER_ARRIVE(mb_free + s * 8);

        // producer: refill stage (c+2)%3 with chunk c+2
        int nc = c + 2;
        if (nc < NCH) {
            int s2 = nc % NSTG;
            if (nc >= NSTG)
                MBARRIER_WAIT_PARITY(mb_free + s2 * 8, ((nc - NSTG) / NSTG) & 1);
            load_chunk(nc);
            CPASYNC_MBAR_ARRIVE(mb_full + s2 * 8);
        }
    }

    // epilogue: bias + relu + residual (pointers recomputed here; cold regs)
    const float* Abase = dir ? g_h1 : g_h0;
    float*       Cbase = dir ? g_h0 : g_h1;
    __half*      Chb   = dir ? g_ta0 : g_ta1;
    int mb0 = mbase + wm * 64, nb0 = nbase + wn * 32;
#pragma unroll
    for (int mf = 0; mf < 4; mf++) {
#pragma unroll
        for (int half = 0; half < 2; half++) {
            int row = mb0 + mf * 16 + half * 8 + g;
            const float* Ar = Abase + (size_t)row * HID + nb0;
            float* Cr = Cbase + (size_t)row * HID + nb0;
            __half* Chr = Chb + (size_t)row * HID + nb0;
#pragma unroll
            for (int nf = 0; nf < 4; nf++) {
                int cl = nf * 8 + 2 * t;
                float2 res = *(const float2*)(Ar + cl);
                float b0 = sbias[wn * 32 + cl];
                float b1 = sbias[wn * 32 + cl + 1];
                float v0 = acc[mf][nf][half * 2 + 0];
                float v1 = acc[mf][nf][half * 2 + 1];
                float2 o;
                o.x = res.x + fmaxf(v0 + b0, 0.0f);
                o.y = res.y + fmaxf(v1 + b1, 0.0f);
                *(float2*)(Cr + cl) = o;
                *(__half2*)(Chr + cl) = __floats2half2_rn(o.x, o.y);
            }
        }
    }
}

// ============================================================
// Kernel 5: LayerNorm + head (N=4). One warp per row. Reads exact fp32.
// ============================================================
__global__ void __launch_bounds__(256) head_kernel(const float* __restrict__ lng,
                                                   const float* __restrict__ lnb,
                                                   const float* __restrict__ hW,
                                                   const float* __restrict__ hb,
                                                   float* __restrict__ out) {
    int w = threadIdx.x >> 5, lane = threadIdx.x & 31;
    int row = blockIdx.x * 8 + w;
    const float4* h4 = (const float4*)(g_h0 + (size_t)row * HID);
    float4 v[16];
    float s = 0.f, ss = 0.f;
#pragma unroll
    for (int i = 0; i < 16; i++) {
        v[i] = h4[i * 32 + lane];
        s += v[i].x + v[i].y + v[i].z + v[i].w;
        ss += v[i].x * v[i].x + v[i].y * v[i].y + v[i].z * v[i].z + v[i].w * v[i].w;
    }
#pragma unroll
    for (int off = 16; off; off >>= 1) {
        s += __shfl_xor_sync(0xffffffffu, s, off);
        ss += __shfl_xor_sync(0xffffffffu, ss, off);
    }
    float mu = s * (1.0f / HID);
    float var = ss * (1.0f / HID) - mu * mu;
    float rs = rsqrtf(var + 1e-5f);
    float a0 = 0.f, a1 = 0.f, a2 = 0.f, a3 = 0.f;
    const float4* g4 = (const float4*)lng;
    const float4* b4 = (const float4*)lnb;
    const float4* w4 = (const float4*)hW;
#pragma unroll 1
    for (int i = 0; i < 16; i++) {
        int k4 = i * 32 + lane;
        float4 gg = g4[k4], bb = b4[k4];
        float hn[4];
        hn[0] = (v[i].x - mu) * rs * gg.x + bb.x;
        hn[1] = (v[i].y - mu) * rs * gg.y + bb.y;
        hn[2] = (v[i].z - mu) * rs * gg.z + bb.z;
        hn[3] = (v[i].w - mu) * rs * gg.w + bb.w;
#pragma unroll
        for (int j = 0; j < 4; j++) {
            float4 wr = w4[k4 * 4 + j];
            a0 += hn[j] * wr.x;
            a1 += hn[j] * wr.y;
            a2 += hn[j] * wr.z;
            a3 += hn[j] * wr.w;
        }
    }
#pragma unroll
    for (int off = 16; off; off >>= 1) {
        a0 += __shfl_xor_sync(0xffffffffu, a0, off);
        a1 += __shfl_xor_sync(0xffffffffu, a1, off);
        a2 += __shfl_xor_sync(0xffffffffu, a2, off);
        a3 += __shfl_xor_sync(0xffffffffu, a3, off);
    }
    if (lane == 0) {
        float4 hbv = *(const float4*)hb;
        float4 o;
        o.x = a0 + hbv.x; o.y = a1 + hbv.y; o.z = a2 + hbv.z; o.w = a3 + hbv.w;
        ((float4*)out)[row] = o;
    }
}

// ============================================================
extern "C" void kernel_launch(void* const* d_in, const int* in_sizes, int n_in,
                              void* d_out, int out_size) {
    const float* x   = (const float*)d_in[0];
    const float* eW  = (const float*)d_in[1];
    const float* eb  = (const float*)d_in[2];
    const float* lW  = (const float*)d_in[3];
    const float* lb  = (const float*)d_in[4];
    const float* lng = (const float*)d_in[5];
    const float* lnb = (const float*)d_in[6];
    const float* hW  = (const float*)d_in[7];
    const float* hb  = (const float*)d_in[8];

    cudaFuncSetAttribute(gemm_kernel, cudaFuncAttributeMaxDynamicSharedMemorySize, DYNSMEM);

    patch_kernel<<<BATCH / 8, 256>>>(x);
    wtrans_kernel<<<dim3(HID / 32, HID / 32, NLAYER), dim3(32, 8)>>>(lW);
    embed_kernel<<<dim3(HID / 128, BATCH / 64), 256>>>(eW, eb);
    for (int l = 0; l < NLAYER; l++)
        gemm_kernel<<<dim3(HID / NT, BATCH / MT), NTHR, DYNSMEM>>>(l, l & 1, lb + (size_t)l * HID);
    head_kernel<<<BATCH / 8, 256>>>(lng, lnb, hW, hb, (float*)d_out);
}

// round 13
// speedup vs baseline: 1.2917x; 1.0220x over previous
#include <cuda_runtime.h>
#include <cuda_fp16.h>
#include <cstdint>
#include <cstddef>

#define BATCH   16384
#define HID     2048
#define NLAYER  8
#define PIN     25

#define MT      128
#define NT      128
#define KC      64                  // 64 fp16 k-values = 128B per row
#define NCH     (HID / KC)          // 32
#define NSTG    3
#define ABYTES  (MT * 128)          // 16384
#define BBYTES  (NT * 128)          // 16384
#define STGB    (ABYTES + BBYTES)   // 32768
#define DYNSMEM (NSTG * STGB + 1024) // 99328  (x2 CTAs = 194.5KB/SM)
#define NTHR    256

// ---------------- device scratch (allocation-free) ----------------
__device__ float  g_h0[(size_t)BATCH * HID];     // exact fp32 activations
__device__ float  g_h1[(size_t)BATCH * HID];
__device__ __half g_ta0[(size_t)BATCH * HID];    // fp16-rounded MMA copies
__device__ __half g_ta1[(size_t)BATCH * HID];
__device__ __half g_wt[(size_t)NLAYER * HID * HID];  // W^T fp16 [l][n][k]
__device__ float  g_patch[(size_t)BATCH * PIN];

// ---------------- helpers ----------------
__device__ __forceinline__ uint32_t smem_u32(const void* p) {
    uint32_t a;
    asm("{ .reg .u64 t; cvta.to.shared.u64 t, %1; cvt.u32.u64 %0, t; }" : "=r"(a) : "l"(p));
    return a;
}

__device__ __forceinline__ void cp_async16(uint32_t s, const void* g) {
    asm volatile("cp.async.cg.shared.global [%0], [%1], 16;" :: "r"(s), "l"(g) : "memory");
}

__device__ __forceinline__ void prefetch_l2(const void* g) {
    asm volatile("prefetch.global.L2 [%0];" :: "l"(g));
}

__device__ __forceinline__ void mma_f16(float* c, const uint32_t* a, const uint32_t* b) {
    asm volatile(
        "mma.sync.aligned.m16n8k16.row.col.f32.f16.f16.f32 "
        "{%0,%1,%2,%3}, {%4,%5,%6,%7}, {%8,%9}, {%0,%1,%2,%3};"
        : "+f"(c[0]), "+f"(c[1]), "+f"(c[2]), "+f"(c[3])
        : "r"(a[0]), "r"(a[1]), "r"(a[2]), "r"(a[3]), "r"(b[0]), "r"(b[1]));
}

#define LDSM4(r0, r1, r2, r3, addr) \
    asm volatile("ldmatrix.sync.aligned.m8n8.x4.shared.b16 {%0,%1,%2,%3}, [%4];" \
        : "=r"(r0), "=r"(r1), "=r"(r2), "=r"(r3) : "r"(addr))

#define MBARRIER_INIT(addr, count) \
    asm volatile("mbarrier.init.shared.b64 [%0], %1;" \
        :: "r"((uint32_t)(addr)), "r"((uint32_t)(count)) : "memory")

#define MBARRIER_ARRIVE(addr) \
    asm volatile("mbarrier.arrive.shared.b64 _, [%0];" \
        :: "r"((uint32_t)(addr)) : "memory")

#define CPASYNC_MBAR_ARRIVE(addr) \
    asm volatile("cp.async.mbarrier.arrive.noinc.shared.b64 [%0];" \
        :: "r"((uint32_t)(addr)) : "memory")

#define MBARRIER_WAIT_PARITY(mbar_smem_addr, phase_parity) do { \
    uint32_t _mbar = (uint32_t)(mbar_smem_addr); \
    uint32_t _parity = (uint32_t)(phase_parity); \
    uint32_t _done; \
    asm volatile( \
        "{\n\t.reg .pred p;\n\t" \
        "mbarrier.try_wait.parity.acquire.cta.shared::cta.b64 p, [%1], %2;\n\t" \
        "selp.b32 %0, 1, 0, p;\n\t}" \
        : "=r"(_done) : "r"(_mbar), "r"(_parity) : "memory"); \
    if (!_done) { \
        asm volatile( \
            "{\n\t.reg .pred P1;\n\t" \
            "WAIT_LOOP_%=:\n\t" \
            "mbarrier.try_wait.parity.acquire.cta.shared::cta.b64 P1, [%0], %1, 0x989680;\n\t" \
            "@P1 bra.uni WAIT_DONE_%=;\n\t" \
            "bra.uni WAIT_LOOP_%=;\n\t" \
            "WAIT_DONE_%=:\n\t}" \
            :: "r"(_mbar), "r"(_parity) : "memory"); \
    } \
} while (0)

// producer-side wait: post-wait accesses are cp.async only (async proxy) -> relaxed
#define MBARRIER_WAIT_PARITY_RELAXED(mbar_smem_addr, phase_parity) do { \
    uint32_t _mbar = (uint32_t)(mbar_smem_addr); \
    uint32_t _parity = (uint32_t)(phase_parity); \
    uint32_t _done; \
    asm volatile( \
        "{\n\t.reg .pred p;\n\t" \
        "mbarrier.try_wait.parity.relaxed.cta.shared::cta.b64 p, [%1], %2, 0x989680;\n\t" \
        "selp.b32 %0, 1, 0, p;\n\t}" \
        : "=r"(_done) : "r"(_mbar), "r"(_parity) : "memory"); \
    if (!_done) { \
        asm volatile( \
            "{\n\t.reg .pred P1;\n\t" \
            "WAIT_LOOP_%=:\n\t" \
            "mbarrier.try_wait.parity.relaxed.cta.shared::cta.b64 P1, [%0], %1, 0x989680;\n\t" \
            "@P1 bra.uni WAIT_DONE_%=;\n\t" \
            "bra.uni WAIT_LOOP_%=;\n\t" \
            "WAIT_DONE_%=:\n\t}" \
            :: "r"(_mbar), "r"(_parity) : "memory"); \
    } \
} while (0)

// ============================================================
// Kernel 1: find agent, extract 5x5 patch (pad -1)
// ============================================================
__global__ void __launch_bounds__(256) patch_kernel(const float* __restrict__ x) {
    int w = threadIdx.x >> 5, lane = threadIdx.x & 31;
    int b = blockIdx.x * 8 + w;
    const float* xb = x + (size_t)b * 1024;
    int found = 0;
#pragma unroll
    for (int s = 0; s < 32; s++)
        if (xb[s * 32 + lane] == 3.0f) found = s * 32 + lane;
#pragma unroll
    for (int off = 16; off; off >>= 1)
        found = max(found, __shfl_xor_sync(0xffffffffu, found, off));
    int row = found >> 5, col = found & 31;
    if (lane < PIN) {
        int r = row + lane / 5 - 2;
        int c = col + lane % 5 - 2;
        float v = (r < 0 || r > 31 || c < 0 || c > 31) ? -1.0f : xb[r * 32 + c];
        g_patch[(size_t)b * PIN + lane] = v;
    }
}

// ============================================================
// Kernel 2: transpose W[l][k][n] -> g_wt[l][n][k] as fp16 (RN)
// ============================================================
__global__ void wtrans_kernel(const float* __restrict__ Wall) {
    __shared__ float t[32][33];
    const float* W = Wall + (size_t)blockIdx.z * HID * HID;
    __half* WT = g_wt + (size_t)blockIdx.z * HID * HID;
    int n0 = blockIdx.x * 32, k0 = blockIdx.y * 32;
    int tx = threadIdx.x, ty = threadIdx.y;
#pragma unroll
    for (int i = 0; i < 4; i++)
        t[ty + i * 8][tx] = W[(size_t)(k0 + ty + i * 8) * HID + n0 + tx];
    __syncthreads();
#pragma unroll
    for (int i = 0; i < 4; i++)
        WT[(size_t)(n0 + ty + i * 8) * HID + k0 + tx] = __float2half_rn(t[tx][ty + i * 8]);
}

// ============================================================
// Kernel 3: embed  h0 = patch . embed_W + embed_b  (K=25); writes fp32 + fp16
// ============================================================
__global__ void __launch_bounds__(256) embed_kernel(const float* __restrict__ eW,
                                                    const float* __restrict__ eb) {
    __shared__ float sp[64][PIN];
    int mb = blockIdx.y * 64, nb = blockIdx.x * 128;
    for (int i = threadIdx.x; i < 64 * PIN; i += 256)
        sp[i / PIN][i % PIN] = g_patch[(size_t)(mb + i / PIN) * PIN + i % PIN];
    __syncthreads();
    int col = threadIdx.x & 127, sg = threadIdx.x >> 7;
    float acc[32];
    float b = eb[nb + col];
#pragma unroll
    for (int s = 0; s < 32; s++) acc[s] = b;
    for (int k = 0; k < PIN; k++) {
        float w = eW[(size_t)k * HID + nb + col];
#pragma unroll
        for (int s = 0; s < 32; s++) acc[s] += sp[sg * 32 + s][k] * w;
    }
#pragma unroll
    for (int s = 0; s < 32; s++) {
        size_t idx = (size_t)(mb + sg * 32 + s) * HID + nb + col;
        g_h0[idx] = acc[s];
        g_ta0[idx] = __float2half_rn(acc[s]);
    }
}

// ============================================================
// Kernel 4: residual layer  C = A + relu(A @ W_l + b_l)
// mma.sync f16 m16n8k16, 128x128 CTA tile, 8 warps (2m x 4n) of 64x32,
// 3-stage mbarrier ring, 2 CTAs/SM, stepped (ks,mf) fragment pipeline.
// R13: relaxed producer waits + residual-tile L2 prefetch at chunk 30.
// ============================================================
__global__ void __launch_bounds__(NTHR, 2) gemm_kernel(int l, int dir,
                                                       const float* __restrict__ bias) {
    const __half* __restrict__ Ah = dir ? g_ta1 : g_ta0;
    const __half* __restrict__ W  = g_wt + (size_t)l * HID * HID;

    extern __shared__ char dynsmem[];
    uint32_t raw = smem_u32(dynsmem);
    uint32_t sbase = (raw + 1023u) & ~1023u;

    __shared__ float sbias[NT];
    __shared__ __align__(8) unsigned long long mbars[2 * NSTG];  // full[0..2], free[0..2]

    int tid = threadIdx.x;
    int mbase = blockIdx.y * MT, nbase = blockIdx.x * NT;
    if (tid < NT) sbias[tid] = bias[nbase + tid];

    uint32_t mb_full = smem_u32(&mbars[0]);
    uint32_t mb_free = smem_u32(&mbars[NSTG]);
    if (tid == 0) {
#pragma unroll
        for (int s = 0; s < NSTG; s++) {
            MBARRIER_INIT(mb_full + s * 8, NTHR);  // all threads' cp.async completions
            MBARRIER_INIT(mb_free + s * 8, 8);     // one arrive per consumer warp
        }
    }
    __syncthreads();   // mbars + sbias visible; only __syncthreads in the kernel

    int wid = tid >> 5, lane = tid & 31;
    int wm = wid & 1, wn = wid >> 1;          // 2 m-warps x 4 n-warps
    int g = lane >> 2, t = lane & 3;

    // ldmatrix lane decomposition
    int rl  = lane & 7;
    int sec = lane >> 3;
    int hi_a = sec >> 1;
    int r8_a = sec & 1;
    int hi_b = sec & 1;
    int nfo_b = sec >> 1;

    uint32_t rowbase_a[4];
#pragma unroll
    for (int mf = 0; mf < 4; mf++)
        rowbase_a[mf] = (uint32_t)(wm * 64 + mf * 16 + r8_a * 8 + rl) * 128;
    uint32_t rowbase_b[2];
#pragma unroll
    for (int p = 0; p < 2; p++)
        rowbase_b[p] = (uint32_t)ABYTES
                     + (uint32_t)(wn * 32 + (2 * p + nfo_b) * 8 + rl) * 128;

    // strength-reduced loader state: per-thread invariant smem offset + global base
    int lrow = tid >> 3, lcid = tid & 7;
    uint32_t aSmOff = (uint32_t)(lrow * 128 + ((lcid ^ (lrow & 7)) * 16));
    uint32_t bSmOff = (uint32_t)ABYTES + aSmOff;   // same row/swizzle pattern
    const __half* aG = Ah + (size_t)(mbase + lrow) * HID + lcid * 8;
    const __half* bG = W  + (size_t)(nbase + lrow) * HID + lcid * 8;

    // residual prefetch base: thread covers 2 x 128B lines of the fp32 tile
    const float* resb = (dir ? g_h1 : g_h0)
                      + (size_t)(mbase + (tid >> 1)) * HID + nbase + (tid & 1) * 64;

    auto load_chunk = [&](int c) {
        uint32_t sa = sbase + (uint32_t)(c % NSTG) * STGB;
        const __half* a = aG + c * KC;
        const __half* b = bG + c * KC;
#pragma unroll
        for (int i = 0; i < 4; i++) {
            cp_async16(sa + aSmOff + i * 4096, a + (size_t)i * 32 * HID);
            cp_async16(sa + bSmOff + i * 4096, b + (size_t)i * 32 * HID);
        }
    };

    float acc[4][4][4];
#pragma unroll
    for (int i = 0; i < 4; i++)
#pragma unroll
        for (int j = 0; j < 4; j++)
#pragma unroll
            for (int q = 0; q < 4; q++) acc[i][j][q] = 0.0f;

    uint32_t fa[2][4];   // 2-slot fa ring (one 16x16 m-fragment per slot)
    uint32_t fb[2][8];   // per-ks double-buffered B fragments (4 n-frags)

    auto ldfa = [&](uint32_t stb, int ks, int mf, int slot) {
        uint32_t offa = (uint32_t)((((2 * ks) | hi_a) ^ rl) * 16);
        LDSM4(fa[slot][0], fa[slot][1], fa[slot][2], fa[slot][3],
              stb + rowbase_a[mf] + offa);
    };
    auto ldfb = [&](uint32_t stb, int ks, int slot) {
        uint32_t offb = (uint32_t)((((2 * ks) | hi_b) ^ rl) * 16);
        LDSM4(fb[slot][0], fb[slot][1], fb[slot][2], fb[slot][3],
              stb + rowbase_b[0] + offb);
        LDSM4(fb[slot][4], fb[slot][5], fb[slot][6], fb[slot][7],
              stb + rowbase_b[1] + offb);
    };

    // prologue: load chunks 0,1; preload chunk 0's first fragments
    load_chunk(0);
    CPASYNC_MBAR_ARRIVE(mb_full + 0 * 8);
    load_chunk(1);
    CPASYNC_MBAR_ARRIVE(mb_full + 1 * 8);
    MBARRIER_WAIT_PARITY(mb_full + 0 * 8, 0);
    ldfa(sbase, 0, 0, 0);
    ldfb(sbase, 0, 0);

    for (int c = 0; c < NCH; c++) {
        int s = c % NSTG;
        uint32_t stb = sbase + (uint32_t)s * STGB;
        int s1 = (c + 1) % NSTG;
        uint32_t stb1 = sbase + (uint32_t)s1 * STGB;
        int p1 = ((c + 1) / NSTG) & 1;
        bool more = (c + 1 < NCH);

#pragma unroll
        for (int ks = 0; ks < 4; ks++) {
            int fbc = ks & 1;
            if (ks == 3 && more)
                MBARRIER_WAIT_PARITY(mb_full + s1 * 8, p1);   // chunk c+1 data ready
#pragma unroll
            for (int mf = 0; mf < 4; mf++) {
                int step = ks * 4 + mf;
                int p = step & 1;
                if (mf == 2) {                  // prefetch next ks's B fragments
                    if (ks < 3) ldfb(stb, ks + 1, fbc ^ 1);
                    else if (more) ldfb(stb1, 0, 0);
                }
                if (step < 15)                  // prefetch next step's A fragment
                    ldfa(stb, (step + 1) >> 2, (step + 1) & 3, p ^ 1);
                else if (more)
                    ldfa(stb1, 0, 0, 0);
#pragma unroll
                for (int nf = 0; nf < 4; nf++)
                    mma_f16(acc[mf][nf], fa[p], &fb[fbc][nf * 2]);
            }
        }
        // this warp is done reading stage s
        if (lane == 0) MBARRIER_ARRIVE(mb_free + s * 8);

        // producer: refill stage (c+2)%3 with chunk c+2
        int nc = c + 2;
        if (nc < NCH) {
            int s2 = nc % NSTG;
            if (nc >= NSTG)
                MBARRIER_WAIT_PARITY_RELAXED(mb_free + s2 * 8, ((nc - NSTG) / NSTG) & 1);
            load_chunk(nc);
            CPASYNC_MBAR_ARRIVE(mb_full + s2 * 8);
        } else if (nc == NCH) {
            // producer idle slot (c == 30): prefetch residual tile into L2
            prefetch_l2(resb);
            prefetch_l2(resb + 32);
        }
    }

    // epilogue: bias + relu + residual (pointers recomputed here; cold regs)
    const float* Abase = dir ? g_h1 : g_h0;
    float*       Cbase = dir ? g_h0 : g_h1;
    __half*      Chb   = dir ? g_ta0 : g_ta1;
    int mb0 = mbase + wm * 64, nb0 = nbase + wn * 32;
#pragma unroll
    for (int mf = 0; mf < 4; mf++) {
#pragma unroll
        for (int half = 0; half < 2; half++) {
            int row = mb0 + mf * 16 + half * 8 + g;
            const float* Ar = Abase + (size_t)row * HID + nb0;
            float* Cr = Cbase + (size_t)row * HID + nb0;
            __half* Chr = Chb + (size_t)row * HID + nb0;
#pragma unroll
            for (int nf = 0; nf < 4; nf++) {
                int cl = nf * 8 + 2 * t;
                float2 res = *(const float2*)(Ar + cl);
                float b0 = sbias[wn * 32 + cl];
                float b1 = sbias[wn * 32 + cl + 1];
                float v0 = acc[mf][nf][half * 2 + 0];
                float v1 = acc[mf][nf][half * 2 + 1];
                float2 o;
                o.x = res.x + fmaxf(v0 + b0, 0.0f);
                o.y = res.y + fmaxf(v1 + b1, 0.0f);
                *(float2*)(Cr + cl) = o;
                *(__half2*)(Chr + cl) = __floats2half2_rn(o.x, o.y);
            }
        }
    }
}

// ============================================================
// Kernel 5: LayerNorm + head (N=4). One warp per row. Reads exact fp32.
// ============================================================
__global__ void __launch_bounds__(256) head_kernel(const float* __restrict__ lng,
                                                   const float* __restrict__ lnb,
                                                   const float* __restrict__ hW,
                                                   const float* __restrict__ hb,
                                                   float* __restrict__ out) {
    int w = threadIdx.x >> 5, lane = threadIdx.x & 31;
    int row = blockIdx.x * 8 + w;
    const float4* h4 = (const float4*)(g_h0 + (size_t)row * HID);
    float4 v[16];
    float s = 0.f, ss = 0.f;
#pragma unroll
    for (int i = 0; i < 16; i++) {
        v[i] = h4[i * 32 + lane];
        s += v[i].x + v[i].y + v[i].z + v[i].w;
        ss += v[i].x * v[i].x + v[i].y * v[i].y + v[i].z * v[i].z + v[i].w * v[i].w;
    }
#pragma unroll
    for (int off = 16; off; off >>= 1) {
        s += __shfl_xor_sync(0xffffffffu, s, off);
        ss += __shfl_xor_sync(0xffffffffu, ss, off);
    }
    float mu = s * (1.0f / HID);
    float var = ss * (1.0f / HID) - mu * mu;
    float rs = rsqrtf(var + 1e-5f);
    float a0 = 0.f, a1 = 0.f, a2 = 0.f, a3 = 0.f;
    const float4* g4 = (const float4*)lng;
    const float4* b4 = (const float4*)lnb;
    const float4* w4 = (const float4*)hW;
#pragma unroll 1
    for (int i = 0; i < 16; i++) {
        int k4 = i * 32 + lane;
        float4 gg = g4[k4], bb = b4[k4];
        float hn[4];
        hn[0] = (v[i].x - mu) * rs * gg.x + bb.x;
        hn[1] = (v[i].y - mu) * rs * gg.y + bb.y;
        hn[2] = (v[i].z - mu) * rs * gg.z + bb.z;
        hn[3] = (v[i].w - mu) * rs * gg.w + bb.w;
#pragma unroll
        for (int j = 0; j < 4; j++) {
            float4 wr = w4[k4 * 4 + j];
            a0 += hn[j] * wr.x;
            a1 += hn[j] * wr.y;
            a2 += hn[j] * wr.z;
            a3 += hn[j] * wr.w;
        }
    }
#pragma unroll
    for (int off = 16; off; off >>= 1) {
        a0 += __shfl_xor_sync(0xffffffffu, a0, off);
        a1 += __shfl_xor_sync(0xffffffffu, a1, off);
        a2 += __shfl_xor_sync(0xffffffffu, a2, off);
        a3 += __shfl_xor_sync(0xffffffffu, a3, off);
    }
    if (lane == 0) {
        float4 hbv = *(const float4*)hb;
        float4 o;
        o.x = a0 + hbv.x; o.y = a1 + hbv.y; o.z = a2 + hbv.z; o.w = a3 + hbv.w;
        ((float4*)out)[row] = o;
    }
}

// ============================================================
extern "C" void kernel_launch(void* const* d_in, const int* in_sizes, int n_in,
                              void* d_out, int out_size) {
    const float* x   = (const float*)d_in[0];
    const float* eW  = (const float*)d_in[1];
    const float* eb  = (const float*)d_in[2];
    const float* lW  = (const float*)d_in[3];
    const float* lb  = (const float*)d_in[4];
    const float* lng = (const float*)d_in[5];
    const float* lnb = (const float*)d_in[6];
    const float* hW  = (const float*)d_in[7];
    const float* hb  = (const float*)d_in[8];

    cudaFuncSetAttribute(gemm_kernel, cudaFuncAttributeMaxDynamicSharedMemorySize, DYNSMEM);

    patch_kernel<<<BATCH / 8, 256>>>(x);
    wtrans_kernel<<<dim3(HID / 32, HID / 32, NLAYER), dim3(32, 8)>>>(lW);
    embed_kernel<<<dim3(HID / 128, BATCH / 64), 256>>>(eW, eb);
    for (int l = 0; l < NLAYER; l++)
        gemm_kernel<<<dim3(HID / NT, BATCH / MT), NTHR, DYNSMEM>>>(l, l & 1, lb + (size_t)l * HID);
    head_kernel<<<BATCH / 8, 256>>>(lng, lnb, hW, hb, (float*)d_out);
}

// round 14
// speedup vs baseline: 1.3350x; 1.0335x over previous
#include <cuda_runtime.h>
#include <cuda_fp16.h>
#include <cstdint>
#include <cstddef>

#define BATCH   16384
#define HID     2048
#define NLAYER  8
#define PIN     25

#define MT      128
#define NT      128
#define KC      64                  // 64 fp16 k-values = 128B per row
#define NCH     (HID / KC)          // 32
#define NSTG    3
#define ABYTES  (MT * 128)          // 16384
#define BBYTES  (NT * 128)          // 16384
#define STGB    (ABYTES + BBYTES)   // 32768
#define DYNSMEM (NSTG * STGB + 1024) // 99328  (x2 CTAs = 194.5KB/SM)
#define NTHR    256
#define MBLKS   (BATCH / MT)        // 128
#define NBLKS   (HID / NT)          // 16

// ---------------- device scratch (allocation-free) ----------------
__device__ float  g_h0[(size_t)BATCH * HID];     // exact fp32 activations
__device__ float  g_h1[(size_t)BATCH * HID];
__device__ __half g_ta0[(size_t)BATCH * HID];    // fp16-rounded MMA copies
__device__ __half g_ta1[(size_t)BATCH * HID];
__device__ __half g_wt[(size_t)NLAYER * HID * HID];  // W^T fp16 [l][n][k]
__device__ float  g_patch[(size_t)BATCH * PIN];
__device__ int    g_flags[NLAYER * MBLKS];       // n-tiles done per (layer, m-block)

// ---------------- helpers ----------------
__device__ __forceinline__ uint32_t smem_u32(const void* p) {
    uint32_t a;
    asm("{ .reg .u64 t; cvta.to.shared.u64 t, %1; cvt.u32.u64 %0, t; }" : "=r"(a) : "l"(p));
    return a;
}

__device__ __forceinline__ void cp_async16(uint32_t s, const void* g) {
    asm volatile("cp.async.cg.shared.global [%0], [%1], 16;" :: "r"(s), "l"(g) : "memory");
}

__device__ __forceinline__ void prefetch_l2(const void* g) {
    asm volatile("prefetch.global.L2 [%0];" :: "l"(g));
}

__device__ __forceinline__ void mma_f16(float* c, const uint32_t* a, const uint32_t* b) {
    asm volatile(
        "mma.sync.aligned.m16n8k16.row.col.f32.f16.f16.f32 "
        "{%0,%1,%2,%3}, {%4,%5,%6,%7}, {%8,%9}, {%0,%1,%2,%3};"
        : "+f"(c[0]), "+f"(c[1]), "+f"(c[2]), "+f"(c[3])
        : "r"(a[0]), "r"(a[1]), "r"(a[2]), "r"(a[3]), "r"(b[0]), "r"(b[1]));
}

#define LDSM4(r0, r1, r2, r3, addr) \
    asm volatile("ldmatrix.sync.aligned.m8n8.x4.shared.b16 {%0,%1,%2,%3}, [%4];" \
        : "=r"(r0), "=r"(r1), "=r"(r2), "=r"(r3) : "r"(addr))

#define MBARRIER_INIT(addr, count) \
    asm volatile("mbarrier.init.shared.b64 [%0], %1;" \
        :: "r"((uint32_t)(addr)), "r"((uint32_t)(count)) : "memory")

#define MBARRIER_ARRIVE(addr) \
    asm volatile("mbarrier.arrive.shared.b64 _, [%0];" \
        :: "r"((uint32_t)(addr)) : "memory")

#define CPASYNC_MBAR_ARRIVE(addr) \
    asm volatile("cp.async.mbarrier.arrive.noinc.shared.b64 [%0];" \
        :: "r"((uint32_t)(addr)) : "memory")

#define MBARRIER_WAIT_PARITY(mbar_smem_addr, phase_parity) do { \
    uint32_t _mbar = (uint32_t)(mbar_smem_addr); \
    uint32_t _parity = (uint32_t)(phase_parity); \
    uint32_t _done; \
    asm volatile( \
        "{\n\t.reg .pred p;\n\t" \
        "mbarrier.try_wait.parity.acquire.cta.shared::cta.b64 p, [%1], %2;\n\t" \
        "selp.b32 %0, 1, 0, p;\n\t}" \
        : "=r"(_done) : "r"(_mbar), "r"(_parity) : "memory"); \
    if (!_done) { \
        asm volatile( \
            "{\n\t.reg .pred P1;\n\t" \
            "WAIT_LOOP_%=:\n\t" \
            "mbarrier.try_wait.parity.acquire.cta.shared::cta.b64 P1, [%0], %1, 0x989680;\n\t" \
            "@P1 bra.uni WAIT_DONE_%=;\n\t" \
            "bra.uni WAIT_LOOP_%=;\n\t" \
            "WAIT_DONE_%=:\n\t}" \
            :: "r"(_mbar), "r"(_parity) : "memory"); \
    } \
} while (0)

// producer-side wait: post-wait accesses are cp.async only (async proxy) -> relaxed
#define MBARRIER_WAIT_PARITY_RELAXED(mbar_smem_addr, phase_parity) do { \
    uint32_t _mbar = (uint32_t)(mbar_smem_addr); \
    uint32_t _parity = (uint32_t)(phase_parity); \
    uint32_t _done; \
    asm volatile( \
        "{\n\t.reg .pred p;\n\t" \
        "mbarrier.try_wait.parity.relaxed.cta.shared::cta.b64 p, [%1], %2, 0x989680;\n\t" \
        "selp.b32 %0, 1, 0, p;\n\t}" \
        : "=r"(_done) : "r"(_mbar), "r"(_parity) : "memory"); \
    if (!_done) { \
        asm volatile( \
            "{\n\t.reg .pred P1;\n\t" \
            "WAIT_LOOP_%=:\n\t" \
            "mbarrier.try_wait.parity.relaxed.cta.shared::cta.b64 P1, [%0], %1, 0x989680;\n\t" \
            "@P1 bra.uni WAIT_DONE_%=;\n\t" \
            "bra.uni WAIT_LOOP_%=;\n\t" \
            "WAIT_DONE_%=:\n\t}" \
            :: "r"(_mbar), "r"(_parity) : "memory"); \
    } \
} while (0)

// ============================================================
// Kernel 0: zero the readiness flags (pure kernel, graph-safe)
// ============================================================
__global__ void zero_flags_kernel() {
    int i = threadIdx.x + blockIdx.x * blockDim.x;
    if (i < NLAYER * MBLKS) g_flags[i] = 0;
}

// ============================================================
// Kernel 1: find agent, extract 5x5 patch (pad -1)
// ============================================================
__global__ void __launch_bounds__(256) patch_kernel(const float* __restrict__ x) {
    int w = threadIdx.x >> 5, lane = threadIdx.x & 31;
    int b = blockIdx.x * 8 + w;
    const float* xb = x + (size_t)b * 1024;
    int found = 0;
#pragma unroll
    for (int s = 0; s < 32; s++)
        if (xb[s * 32 + lane] == 3.0f) found = s * 32 + lane;
#pragma unroll
    for (int off = 16; off; off >>= 1)
        found = max(found, __shfl_xor_sync(0xffffffffu, found, off));
    int row = found >> 5, col = found & 31;
    if (lane < PIN) {
        int r = row + lane / 5 - 2;
        int c = col + lane % 5 - 2;
        float v = (r < 0 || r > 31 || c < 0 || c > 31) ? -1.0f : xb[r * 32 + c];
        g_patch[(size_t)b * PIN + lane] = v;
    }
}

// ============================================================
// Kernel 2: transpose W[l][k][n] -> g_wt[l][n][k] as fp16 (RN)
// ============================================================
__global__ void wtrans_kernel(const float* __restrict__ Wall) {
    __shared__ float t[32][33];
    const float* W = Wall + (size_t)blockIdx.z * HID * HID;
    __half* WT = g_wt + (size_t)blockIdx.z * HID * HID;
    int n0 = blockIdx.x * 32, k0 = blockIdx.y * 32;
    int tx = threadIdx.x, ty = threadIdx.y;
#pragma unroll
    for (int i = 0; i < 4; i++)
        t[ty + i * 8][tx] = W[(size_t)(k0 + ty + i * 8) * HID + n0 + tx];
    __syncthreads();
#pragma unroll
    for (int i = 0; i < 4; i++)
        WT[(size_t)(n0 + ty + i * 8) * HID + k0 + tx] = __float2half_rn(t[tx][ty + i * 8]);
}

// ============================================================
// Kernel 3: embed  h0 = patch . embed_W + embed_b  (K=25); writes fp32 + fp16
// ============================================================
__global__ void __launch_bounds__(256) embed_kernel(const float* __restrict__ eW,
                                                    const float* __restrict__ eb) {
    __shared__ float sp[64][PIN];
    int mb = blockIdx.y * 64, nb = blockIdx.x * 128;
    for (int i = threadIdx.x; i < 64 * PIN; i += 256)
        sp[i / PIN][i % PIN] = g_patch[(size_t)(mb + i / PIN) * PIN + i % PIN];
    __syncthreads();
    int col = threadIdx.x & 127, sg = threadIdx.x >> 7;
    float acc[32];
    float b = eb[nb + col];
#pragma unroll
    for (int s = 0; s < 32; s++) acc[s] = b;
    for (int k = 0; k < PIN; k++) {
        float w = eW[(size_t)k * HID + nb + col];
#pragma unroll
        for (int s = 0; s < 32; s++) acc[s] += sp[sg * 32 + s][k] * w;
    }
#pragma unroll
    for (int s = 0; s < 32; s++) {
        size_t idx = (size_t)(mb + sg * 32 + s) * HID + nb + col;
        g_h0[idx] = acc[s];
        g_ta0[idx] = __float2half_rn(acc[s]);
    }
}

// ============================================================
// Kernel 4: ALL residual layers fused:  C = A + relu(A @ W_l + b_l)
// grid = NLAYER * MBLKS * NBLKS; bid -> (l, m, n). Cross-layer dependency
// via g_flags[l-1][m] (16 producer n-tiles; release = fence+atomicAdd,
// acquire = relaxed spin + fence). Launch order is monotone in bid and the
// producer->consumer bid gap (>=2033) far exceeds the resident window, so
// the spin is a fast-path safety check; interior launch drains vanish.
// Inner loop identical to R13 (mbarrier ring, stepped fragment pipeline).
// ============================================================
__global__ void __launch_bounds__(NTHR, 2) gemm_all_kernel(const float* __restrict__ bias_all) {
    int bid = blockIdx.x;
    int l = bid >> 11;                       // 2048 tiles per layer
    int r = bid & 2047;
    int mblk = r >> 4, nblk = r & 15;
    int dir = l & 1;
    const float* bias = bias_all + (size_t)l * HID;

    const __half* __restrict__ Ah = dir ? g_ta1 : g_ta0;
    const __half* __restrict__ W  = g_wt + (size_t)l * HID * HID;

    extern __shared__ char dynsmem[];
    uint32_t raw = smem_u32(dynsmem);
    uint32_t sbase = (raw + 1023u) & ~1023u;

    __shared__ float sbias[NT];
    __shared__ __align__(8) unsigned long long mbars[2 * NSTG];  // full[0..2], free[0..2]

    int tid = threadIdx.x;
    int mbase = mblk * MT, nbase = nblk * NT;
    if (tid < NT) sbias[tid] = bias[nbase + tid];

    uint32_t mb_full = smem_u32(&mbars[0]);
    uint32_t mb_free = smem_u32(&mbars[NSTG]);
    if (tid == 0) {
#pragma unroll
        for (int s = 0; s < NSTG; s++) {
            MBARRIER_INIT(mb_full + s * 8, NTHR);
            MBARRIER_INIT(mb_free + s * 8, 8);
        }
    }

    // cross-layer dependency: wait for all 16 n-tiles of (l-1, mblk)
    if (l > 0) {
        if (tid == 0) {
            int* f = &g_flags[(l - 1) * MBLKS + mblk];
            while (atomicAdd(f, 0) < NBLKS) __nanosleep(64);
            __threadfence();                 // acquire
        }
    }
    __syncthreads();   // mbars + sbias + dependency visible

    int wid = tid >> 5, lane = tid & 31;
    int wm = wid & 1, wn = wid >> 1;          // 2 m-warps x 4 n-warps
    int g = lane >> 2, t = lane & 3;

    int rl  = lane & 7;
    int sec = lane >> 3;
    int hi_a = sec >> 1;
    int r8_a = sec & 1;
    int hi_b = sec & 1;
    int nfo_b = sec >> 1;

    uint32_t rowbase_a[4];
#pragma unroll
    for (int mf = 0; mf < 4; mf++)
        rowbase_a[mf] = (uint32_t)(wm * 64 + mf * 16 + r8_a * 8 + rl) * 128;
    uint32_t rowbase_b[2];
#pragma unroll
    for (int p = 0; p < 2; p++)
        rowbase_b[p] = (uint32_t)ABYTES
                     + (uint32_t)(wn * 32 + (2 * p + nfo_b) * 8 + rl) * 128;

    int lrow = tid >> 3, lcid = tid & 7;
    uint32_t aSmOff = (uint32_t)(lrow * 128 + ((lcid ^ (lrow & 7)) * 16));
    uint32_t bSmOff = (uint32_t)ABYTES + aSmOff;
    const __half* aG = Ah + (size_t)(mbase + lrow) * HID + lcid * 8;
    const __half* bG = W  + (size_t)(nbase + lrow) * HID + lcid * 8;

    const float* resb = (dir ? g_h1 : g_h0)
                      + (size_t)(mbase + (tid >> 1)) * HID + nbase + (tid & 1) * 64;

    auto load_chunk = [&](int c) {
        uint32_t sa = sbase + (uint32_t)(c % NSTG) * STGB;
        const __half* a = aG + c * KC;
        const __half* b = bG + c * KC;
#pragma unroll
        for (int i = 0; i < 4; i++) {
            cp_async16(sa + aSmOff + i * 4096, a + (size_t)i * 32 * HID);
            cp_async16(sa + bSmOff + i * 4096, b + (size_t)i * 32 * HID);
        }
    };

    float acc[4][4][4];
#pragma unroll
    for (int i = 0; i < 4; i++)
#pragma unroll
        for (int j = 0; j < 4; j++)
#pragma unroll
            for (int q = 0; q < 4; q++) acc[i][j][q] = 0.0f;

    uint32_t fa[2][4];
    uint32_t fb[2][8];

    auto ldfa = [&](uint32_t stb, int ks, int mf, int slot) {
        uint32_t offa = (uint32_t)((((2 * ks) | hi_a) ^ rl) * 16);
        LDSM4(fa[slot][0], fa[slot][1], fa[slot][2], fa[slot][3],
              stb + rowbase_a[mf] + offa);
    };
    auto ldfb = [&](uint32_t stb, int ks, int slot) {
        uint32_t offb = (uint32_t)((((2 * ks) | hi_b) ^ rl) * 16);
        LDSM4(fb[slot][0], fb[slot][1], fb[slot][2], fb[slot][3],
              stb + rowbase_b[0] + offb);
        LDSM4(fb[slot][4], fb[slot][5], fb[slot][6], fb[slot][7],
              stb + rowbase_b[1] + offb);
    };

    load_chunk(0);
    CPASYNC_MBAR_ARRIVE(mb_full + 0 * 8);
    load_chunk(1);
    CPASYNC_MBAR_ARRIVE(mb_full + 1 * 8);
    MBARRIER_WAIT_PARITY(mb_full + 0 * 8, 0);
    ldfa(sbase, 0, 0, 0);
    ldfb(sbase, 0, 0);

    for (int c = 0; c < NCH; c++) {
        int s = c % NSTG;
        uint32_t stb = sbase + (uint32_t)s * STGB;
        int s1 = (c + 1) % NSTG;
        uint32_t stb1 = sbase + (uint32_t)s1 * STGB;
        int p1 = ((c + 1) / NSTG) & 1;
        bool more = (c + 1 < NCH);

#pragma unroll
        for (int ks = 0; ks < 4; ks++) {
            int fbc = ks & 1;
            if (ks == 3 && more)
                MBARRIER_WAIT_PARITY(mb_full + s1 * 8, p1);
#pragma unroll
            for (int mf = 0; mf < 4; mf++) {
                int step = ks * 4 + mf;
                int p = step & 1;
                if (mf == 2) {
                    if (ks < 3) ldfb(stb, ks + 1, fbc ^ 1);
                    else if (more) ldfb(stb1, 0, 0);
                }
                if (step < 15)
                    ldfa(stb, (step + 1) >> 2, (step + 1) & 3, p ^ 1);
                else if (more)
                    ldfa(stb1, 0, 0, 0);
#pragma unroll
                for (int nf = 0; nf < 4; nf++)
                    mma_f16(acc[mf][nf], fa[p], &fb[fbc][nf * 2]);
            }
        }
        if (lane == 0) MBARRIER_ARRIVE(mb_free + s * 8);

        int nc = c + 2;
        if (nc < NCH) {
            int s2 = nc % NSTG;
            if (nc >= NSTG)
                MBARRIER_WAIT_PARITY_RELAXED(mb_free + s2 * 8, ((nc - NSTG) / NSTG) & 1);
            load_chunk(nc);
            CPASYNC_MBAR_ARRIVE(mb_full + s2 * 8);
        } else if (nc == NCH) {
            prefetch_l2(resb);
            prefetch_l2(resb + 32);
        }
    }

    // epilogue: bias + relu + residual
    const float* Abase = dir ? g_h1 : g_h0;
    float*       Cbase = dir ? g_h0 : g_h1;
    __half*      Chb   = dir ? g_ta0 : g_ta1;
    int mb0 = mbase + wm * 64, nb0 = nbase + wn * 32;
#pragma unroll
    for (int mf = 0; mf < 4; mf++) {
#pragma unroll
        for (int half = 0; half < 2; half++) {
            int row = mb0 + mf * 16 + half * 8 + g;
            const float* Ar = Abase + (size_t)row * HID + nb0;
            float* Cr = Cbase + (size_t)row * HID + nb0;
            __half* Chr = Chb + (size_t)row * HID + nb0;
#pragma unroll
            for (int nf = 0; nf < 4; nf++) {
                int cl = nf * 8 + 2 * t;
                float2 res = *(const float2*)(Ar + cl);
                float b0 = sbias[wn * 32 + cl];
                float b1 = sbias[wn * 32 + cl + 1];
                float v0 = acc[mf][nf][half * 2 + 0];
                float v1 = acc[mf][nf][half * 2 + 1];
                float2 o;
                o.x = res.x + fmaxf(v0 + b0, 0.0f);
                o.y = res.y + fmaxf(v1 + b1, 0.0f);
                *(float2*)(Cr + cl) = o;
                *(__half2*)(Chr + cl) = __floats2half2_rn(o.x, o.y);
            }
        }
    }

    // publish this tile (release)
    __syncthreads();
    if (tid == 0) {
        __threadfence();
        atomicAdd(&g_flags[l * MBLKS + mblk], 1);
    }
}

// ============================================================
// Kernel 5: LayerNorm + head (N=4). One warp per row. Reads exact fp32.
// ============================================================
__global__ void __launch_bounds__(256) head_kernel(const float* __restrict__ lng,
                                                   const float* __restrict__ lnb,
                                                   const float* __restrict__ hW,
                                                   const float* __restrict__ hb,
                                                   float* __restrict__ out) {
    int w = threadIdx.x >> 5, lane = threadIdx.x & 31;
    int row = blockIdx.x * 8 + w;
    const float4* h4 = (const float4*)(g_h0 + (size_t)row * HID);
    float4 v[16];
    float s = 0.f, ss = 0.f;
#pragma unroll
    for (int i = 0; i < 16; i++) {
        v[i] = h4[i * 32 + lane];
        s += v[i].x + v[i].y + v[i].z + v[i].w;
        ss += v[i].x * v[i].x + v[i].y * v[i].y + v[i].z * v[i].z + v[i].w * v[i].w;
    }
#pragma unroll
    for (int off = 16; off; off >>= 1) {
        s += __shfl_xor_sync(0xffffffffu, s, off);
        ss += __shfl_xor_sync(0xffffffffu, ss, off);
    }
    float mu = s * (1.0f / HID);
    float var = ss * (1.0f / HID) - mu * mu;
    float rs = rsqrtf(var + 1e-5f);
    float a0 = 0.f, a1 = 0.f, a2 = 0.f, a3 = 0.f;
    const float4* g4 = (const float4*)lng;
    const float4* b4 = (const float4*)lnb;
    const float4* w4 = (const float4*)hW;
#pragma unroll 1
    for (int i = 0; i < 16; i++) {
        int k4 = i * 32 + lane;
        float4 gg = g4[k4], bb = b4[k4];
        float hn[4];
        hn[0] = (v[i].x - mu) * rs * gg.x + bb.x;
        hn[1] = (v[i].y - mu) * rs * gg.y + bb.y;
        hn[2] = (v[i].z - mu) * rs * gg.z + bb.z;
        hn[3] = (v[i].w - mu) * rs * gg.w + bb.w;
#pragma unroll
        for (int j = 0; j < 4; j++) {
            float4 wr = w4[k4 * 4 + j];
            a0 += hn[j] * wr.x;
            a1 += hn[j] * wr.y;
            a2 += hn[j] * wr.z;
            a3 += hn[j] * wr.w;
        }
    }
#pragma unroll
    for (int off = 16; off; off >>= 1) {
        a0 += __shfl_xor_sync(0xffffffffu, a0, off);
        a1 += __shfl_xor_sync(0xffffffffu, a1, off);
        a2 += __shfl_xor_sync(0xffffffffu, a2, off);
        a3 += __shfl_xor_sync(0xffffffffu, a3, off);
    }
    if (lane == 0) {
        float4 hbv = *(const float4*)hb;
        float4 o;
        o.x = a0 + hbv.x; o.y = a1 + hbv.y; o.z = a2 + hbv.z; o.w = a3 + hbv.w;
        ((float4*)out)[row] = o;
    }
}

// ============================================================
extern "C" void kernel_launch(void* const* d_in, const int* in_sizes, int n_in,
                              void* d_out, int out_size) {
    const float* x   = (const float*)d_in[0];
    const float* eW  = (const float*)d_in[1];
    const float* eb  = (const float*)d_in[2];
    const float* lW  = (const float*)d_in[3];
    const float* lb  = (const float*)d_in[4];
    const float* lng = (const float*)d_in[5];
    const float* lnb = (const float*)d_in[6];
    const float* hW  = (const float*)d_in[7];
    const float* hb  = (const float*)d_in[8];

    cudaFuncSetAttribute(gemm_all_kernel, cudaFuncAttributeMaxDynamicSharedMemorySize, DYNSMEM);

    zero_flags_kernel<<<(NLAYER * MBLKS + 255) / 256, 256>>>();
    patch_kernel<<<BATCH / 8, 256>>>(x);
    wtrans_kernel<<<dim3(HID / 32, HID / 32, NLAYER), dim3(32, 8)>>>(lW);
    embed_kernel<<<dim3(HID / 128, BATCH / 64), 256>>>(eW, eb);
    gemm_all_kernel<<<NLAYER * MBLKS * NBLKS, NTHR, DYNSMEM>>>(lb);
    head_kernel<<<BATCH / 8, 256>>>(lng, lnb, hW, hb, (float*)d_out);
}

// round 15
// speedup vs baseline: 1.3619x; 1.0202x over previous
#include <cuda_runtime.h>
#include <cuda_fp16.h>
#include <cstdint>
#include <cstddef>

#define BATCH   16384
#define HID     2048
#define NLAYER  8
#define PIN     25

#define MT      128
#define NT      128
#define KC      64                  // 64 fp16 k-values = 128B per row
#define NCH     (HID / KC)          // 32
#define NSTG    3
#define ABYTES  (MT * 128)          // 16384
#define BBYTES  (NT * 128)          // 16384
#define STGB    (ABYTES + BBYTES)   // 32768
#define DYNSMEM (NSTG * STGB + 1024) // 99328  (x2 CTAs = 194.5KB/SM)
#define NTHR    256
#define MBLKS   (BATCH / MT)        // 128
#define NBLKS   (HID / NT)          // 16

// ---------------- device scratch (allocation-free) ----------------
__device__ float  g_h0[(size_t)BATCH * HID];     // exact fp32 activations
__device__ float  g_h1[(size_t)BATCH * HID];
__device__ __half g_ta0[(size_t)BATCH * HID];    // fp16-rounded MMA copies
__device__ __half g_ta1[(size_t)BATCH * HID];
__device__ __half g_wt[(size_t)NLAYER * HID * HID];  // W^T fp16 [l][n][k]
__device__ float  g_patch[(size_t)BATCH * PIN];
__device__ int    g_flags[NLAYER * MBLKS];       // n-tiles done per (layer, m-block)

// ---------------- helpers ----------------
__device__ __forceinline__ uint32_t smem_u32(const void* p) {
    uint32_t a;
    asm("{ .reg .u64 t; cvta.to.shared.u64 t, %1; cvt.u32.u64 %0, t; }" : "=r"(a) : "l"(p));
    return a;
}

__device__ __forceinline__ void cp_async16(uint32_t s, const void* g) {
    asm volatile("cp.async.cg.shared.global [%0], [%1], 16;" :: "r"(s), "l"(g) : "memory");
}

__device__ __forceinline__ void prefetch_l2(const void* g) {
    asm volatile("prefetch.global.L2 [%0];" :: "l"(g));
}

__device__ __forceinline__ void mma_f16(float* c, const uint32_t* a, const uint32_t* b) {
    asm volatile(
        "mma.sync.aligned.m16n8k16.row.col.f32.f16.f16.f32 "
        "{%0,%1,%2,%3}, {%4,%5,%6,%7}, {%8,%9}, {%0,%1,%2,%3};"
        : "+f"(c[0]), "+f"(c[1]), "+f"(c[2]), "+f"(c[3])
        : "r"(a[0]), "r"(a[1]), "r"(a[2]), "r"(a[3]), "r"(b[0]), "r"(b[1]));
}

#define LDSM4(r0, r1, r2, r3, addr) \
    asm volatile("ldmatrix.sync.aligned.m8n8.x4.shared.b16 {%0,%1,%2,%3}, [%4];" \
        : "=r"(r0), "=r"(r1), "=r"(r2), "=r"(r3) : "r"(addr))

#define MBARRIER_INIT(addr, count) \
    asm volatile("mbarrier.init.shared.b64 [%0], %1;" \
        :: "r"((uint32_t)(addr)), "r"((uint32_t)(count)) : "memory")

#define MBARRIER_ARRIVE(addr) \
    asm volatile("mbarrier.arrive.shared.b64 _, [%0];" \
        :: "r"((uint32_t)(addr)) : "memory")

#define CPASYNC_MBAR_ARRIVE(addr) \
    asm volatile("cp.async.mbarrier.arrive.noinc.shared.b64 [%0];" \
        :: "r"((uint32_t)(addr)) : "memory")

#define MBARRIER_WAIT_PARITY(mbar_smem_addr, phase_parity) do { \
    uint32_t _mbar = (uint32_t)(mbar_smem_addr); \
    uint32_t _parity = (uint32_t)(phase_parity); \
    uint32_t _done; \
    asm volatile( \
        "{\n\t.reg .pred p;\n\t" \
        "mbarrier.try_wait.parity.acquire.cta.shared::cta.b64 p, [%1], %2;\n\t" \
        "selp.b32 %0, 1, 0, p;\n\t}" \
        : "=r"(_done) : "r"(_mbar), "r"(_parity) : "memory"); \
    if (!_done) { \
        asm volatile( \
            "{\n\t.reg .pred P1;\n\t" \
            "WAIT_LOOP_%=:\n\t" \
            "mbarrier.try_wait.parity.acquire.cta.shared::cta.b64 P1, [%0], %1, 0x989680;\n\t" \
            "@P1 bra.uni WAIT_DONE_%=;\n\t" \
            "bra.uni WAIT_LOOP_%=;\n\t" \
            "WAIT_DONE_%=:\n\t}" \
            :: "r"(_mbar), "r"(_parity) : "memory"); \
    } \
} while (0)

// producer-side wait: post-wait accesses are cp.async only (async proxy) -> relaxed
#define MBARRIER_WAIT_PARITY_RELAXED(mbar_smem_addr, phase_parity) do { \
    uint32_t _mbar = (uint32_t)(mbar_smem_addr); \
    uint32_t _parity = (uint32_t)(phase_parity); \
    uint32_t _done; \
    asm volatile( \
        "{\n\t.reg .pred p;\n\t" \
        "mbarrier.try_wait.parity.relaxed.cta.shared::cta.b64 p, [%1], %2, 0x989680;\n\t" \
        "selp.b32 %0, 1, 0, p;\n\t}" \
        : "=r"(_done) : "r"(_mbar), "r"(_parity) : "memory"); \
    if (!_done) { \
        asm volatile( \
            "{\n\t.reg .pred P1;\n\t" \
            "WAIT_LOOP_%=:\n\t" \
            "mbarrier.try_wait.parity.relaxed.cta.shared::cta.b64 P1, [%0], %1, 0x989680;\n\t" \
            "@P1 bra.uni WAIT_DONE_%=;\n\t" \
            "bra.uni WAIT_LOOP_%=;\n\t" \
            "WAIT_DONE_%=:\n\t}" \
            :: "r"(_mbar), "r"(_parity) : "memory"); \
    } \
} while (0)

// ============================================================
// Kernel 0: zero the readiness flags (pure kernel, graph-safe)
// ============================================================
__global__ void zero_flags_kernel() {
    int i = threadIdx.x + blockIdx.x * blockDim.x;
    if (i < NLAYER * MBLKS) g_flags[i] = 0;
}

// ============================================================
// Kernel 1: find agent, extract 5x5 patch (pad -1)
// ============================================================
__global__ void __launch_bounds__(256) patch_kernel(const float* __restrict__ x) {
    int w = threadIdx.x >> 5, lane = threadIdx.x & 31;
    int b = blockIdx.x * 8 + w;
    const float* xb = x + (size_t)b * 1024;
    int found = 0;
#pragma unroll
    for (int s = 0; s < 32; s++)
        if (xb[s * 32 + lane] == 3.0f) found = s * 32 + lane;
#pragma unroll
    for (int off = 16; off; off >>= 1)
        found = max(found, __shfl_xor_sync(0xffffffffu, found, off));
    int row = found >> 5, col = found & 31;
    if (lane < PIN) {
        int r = row + lane / 5 - 2;
        int c = col + lane % 5 - 2;
        float v = (r < 0 || r > 31 || c < 0 || c > 31) ? -1.0f : xb[r * 32 + c];
        g_patch[(size_t)b * PIN + lane] = v;
    }
}

// ============================================================
// Kernel 2: transpose W[l][k][n] -> g_wt[l][n][k] as fp16 (RN)
// ============================================================
__global__ void wtrans_kernel(const float* __restrict__ Wall) {
    __shared__ float t[32][33];
    const float* W = Wall + (size_t)blockIdx.z * HID * HID;
    __half* WT = g_wt + (size_t)blockIdx.z * HID * HID;
    int n0 = blockIdx.x * 32, k0 = blockIdx.y * 32;
    int tx = threadIdx.x, ty = threadIdx.y;
#pragma unroll
    for (int i = 0; i < 4; i++)
        t[ty + i * 8][tx] = W[(size_t)(k0 + ty + i * 8) * HID + n0 + tx];
    __syncthreads();
#pragma unroll
    for (int i = 0; i < 4; i++)
        WT[(size_t)(n0 + ty + i * 8) * HID + k0 + tx] = __float2half_rn(t[tx][ty + i * 8]);
}

// ============================================================
// Kernel 3: embed  h0 = patch . embed_W + embed_b  (K=25).
// Register-blocked: 4 cols x 8 rows per thread; 1 broadcast LDS feeds
// 4 FMAs; float4/half2 vectorized stores. Same k-accumulation order as
// before -> bit-identical results.
// ============================================================
__global__ void __launch_bounds__(256) embed_kernel(const float* __restrict__ eW,
                                                    const float* __restrict__ eb) {
    __shared__ float sp[64][PIN];
    int mb = blockIdx.y * 64, nb = blockIdx.x * 128;
    for (int i = threadIdx.x; i < 64 * PIN; i += 256)
        sp[i / PIN][i % PIN] = g_patch[(size_t)(mb + i / PIN) * PIN + i % PIN];
    __syncthreads();

    int tc = threadIdx.x & 31;          // 32 col-groups of 4 cols
    int sg = threadIdx.x >> 5;          // 8 row-groups of 8 rows (uniform per warp)
    int col = nb + tc * 4;

    float4 bv = *(const float4*)(eb + col);
    float acc[8][4];
#pragma unroll
    for (int s = 0; s < 8; s++) {
        acc[s][0] = bv.x; acc[s][1] = bv.y; acc[s][2] = bv.z; acc[s][3] = bv.w;
    }

    for (int k = 0; k < PIN; k++) {
        float4 w = *(const float4*)(eW + (size_t)k * HID + col);
#pragma unroll
        for (int s = 0; s < 8; s++) {
            float a = sp[sg * 8 + s][k];      // warp-broadcast
            acc[s][0] += a * w.x;
            acc[s][1] += a * w.y;
            acc[s][2] += a * w.z;
            acc[s][3] += a * w.w;
        }
    }

#pragma unroll
    for (int s = 0; s < 8; s++) {
        int row = mb + sg * 8 + s;
        float* h = g_h0 + (size_t)row * HID + col;
        __half* th = g_ta0 + (size_t)row * HID + col;
        *(float4*)h = make_float4(acc[s][0], acc[s][1], acc[s][2], acc[s][3]);
        *(__half2*)(th)     = __floats2half2_rn(acc[s][0], acc[s][1]);
        *(__half2*)(th + 2) = __floats2half2_rn(acc[s][2], acc[s][3]);
    }
}

// ============================================================
// Kernel 4: ALL residual layers fused:  C = A + relu(A @ W_l + b_l)
// grid = NLAYER * MBLKS * NBLKS; bid -> (l, m, n). Cross-layer dependency
// via g_flags[l-1][m]. Inner loop identical to R13/R14.
// ============================================================
__global__ void __launch_bounds__(NTHR, 2) gemm_all_kernel(const float* __restrict__ bias_all) {
    int bid = blockIdx.x;
    int l = bid >> 11;                       // 2048 tiles per layer
    int r = bid & 2047;
    int mblk = r >> 4, nblk = r & 15;
    int dir = l & 1;
    const float* bias = bias_all + (size_t)l * HID;

    const __half* __restrict__ Ah = dir ? g_ta1 : g_ta0;
    const __half* __restrict__ W  = g_wt + (size_t)l * HID * HID;

    extern __shared__ char dynsmem[];
    uint32_t raw = smem_u32(dynsmem);
    uint32_t sbase = (raw + 1023u) & ~1023u;

    __shared__ float sbias[NT];
    __shared__ __align__(8) unsigned long long mbars[2 * NSTG];  // full[0..2], free[0..2]

    int tid = threadIdx.x;
    int mbase = mblk * MT, nbase = nblk * NT;
    if (tid < NT) sbias[tid] = bias[nbase + tid];

    uint32_t mb_full = smem_u32(&mbars[0]);
    uint32_t mb_free = smem_u32(&mbars[NSTG]);
    if (tid == 0) {
#pragma unroll
        for (int s = 0; s < NSTG; s++) {
            MBARRIER_INIT(mb_full + s * 8, NTHR);
            MBARRIER_INIT(mb_free + s * 8, 8);
        }
    }

    // cross-layer dependency: wait for all 16 n-tiles of (l-1, mblk)
    if (l > 0) {
        if (tid == 0) {
            int* f = &g_flags[(l - 1) * MBLKS + mblk];
            while (atomicAdd(f, 0) < NBLKS) __nanosleep(64);
            __threadfence();                 // acquire
        }
    }
    __syncthreads();   // mbars + sbias + dependency visible

    int wid = tid >> 5, lane = tid & 31;
    int wm = wid & 1, wn = wid >> 1;          // 2 m-warps x 4 n-warps
    int g = lane >> 2, t = lane & 3;

    int rl  = lane & 7;
    int sec = lane >> 3;
    int hi_a = sec >> 1;
    int r8_a = sec & 1;
    int hi_b = sec & 1;
    int nfo_b = sec >> 1;

    uint32_t rowbase_a[4];
#pragma unroll
    for (int mf = 0; mf < 4; mf++)
        rowbase_a[mf] = (uint32_t)(wm * 64 + mf * 16 + r8_a * 8 + rl) * 128;
    uint32_t rowbase_b[2];
#pragma unroll
    for (int p = 0; p < 2; p++)
        rowbase_b[p] = (uint32_t)ABYTES
                     + (uint32_t)(wn * 32 + (2 * p + nfo_b) * 8 + rl) * 128;

    int lrow = tid >> 3, lcid = tid & 7;
    uint32_t aSmOff = (uint32_t)(lrow * 128 + ((lcid ^ (lrow & 7)) * 16));
    uint32_t bSmOff = (uint32_t)ABYTES + aSmOff;
    const __half* aG = Ah + (size_t)(mbase + lrow) * HID + lcid * 8;
    const __half* bG = W  + (size_t)(nbase + lrow) * HID + lcid * 8;

    const float* resb = (dir ? g_h1 : g_h0)
                      + (size_t)(mbase + (tid >> 1)) * HID + nbase + (tid & 1) * 64;

    auto load_chunk = [&](int c) {
        uint32_t sa = sbase + (uint32_t)(c % NSTG) * STGB;
        const __half* a = aG + c * KC;
        const __half* b = bG + c * KC;
#pragma unroll
        for (int i = 0; i < 4; i++) {
            cp_async16(sa + aSmOff + i * 4096, a + (size_t)i * 32 * HID);
            cp_async16(sa + bSmOff + i * 4096, b + (size_t)i * 32 * HID);
        }
    };

    float acc[4][4][4];
#pragma unroll
    for (int i = 0; i < 4; i++)
#pragma unroll
        for (int j = 0; j < 4; j++)
#pragma unroll
            for (int q = 0; q < 4; q++) acc[i][j][q] = 0.0f;

    uint32_t fa[2][4];
    uint32_t fb[2][8];

    auto ldfa = [&](uint32_t stb, int ks, int mf, int slot) {
        uint32_t offa = (uint32_t)((((2 * ks) | hi_a) ^ rl) * 16);
        LDSM4(fa[slot][0], fa[slot][1], fa[slot][2], fa[slot][3],
              stb + rowbase_a[mf] + offa);
    };
    auto ldfb = [&](uint32_t stb, int ks, int slot) {
        uint32_t offb = (uint32_t)((((2 * ks) | hi_b) ^ rl) * 16);
        LDSM4(fb[slot][0], fb[slot][1], fb[slot][2], fb[slot][3],
              stb + rowbase_b[0] + offb);
        LDSM4(fb[slot][4], fb[slot][5], fb[slot][6], fb[slot][7],
              stb + rowbase_b[1] + offb);
    };

    load_chunk(0);
    CPASYNC_MBAR_ARRIVE(mb_full + 0 * 8);
    load_chunk(1);
    CPASYNC_MBAR_ARRIVE(mb_full + 1 * 8);
    MBARRIER_WAIT_PARITY(mb_full + 0 * 8, 0);
    ldfa(sbase, 0, 0, 0);
    ldfb(sbase, 0, 0);

    for (int c = 0; c < NCH; c++) {
        int s = c % NSTG;
        uint32_t stb = sbase + (uint32_t)s * STGB;
        int s1 = (c + 1) % NSTG;
        uint32_t stb1 = sbase + (uint32_t)s1 * STGB;
        int p1 = ((c + 1) / NSTG) & 1;
        bool more = (c + 1 < NCH);

#pragma unroll
        for (int ks = 0; ks < 4; ks++) {
            int fbc = ks & 1;
            if (ks == 3 && more)
                MBARRIER_WAIT_PARITY(mb_full + s1 * 8, p1);
#pragma unroll
            for (int mf = 0; mf < 4; mf++) {
                int step = ks * 4 + mf;
                int p = step & 1;
                if (mf == 2) {
                    if (ks < 3) ldfb(stb, ks + 1, fbc ^ 1);
                    else if (more) ldfb(stb1, 0, 0);
                }
                if (step < 15)
                    ldfa(stb, (step + 1) >> 2, (step + 1) & 3, p ^ 1);
                else if (more)
                    ldfa(stb1, 0, 0, 0);
#pragma unroll
                for (int nf = 0; nf < 4; nf++)
                    mma_f16(acc[mf][nf], fa[p], &fb[fbc][nf * 2]);
            }
        }
        if (lane == 0) MBARRIER_ARRIVE(mb_free + s * 8);

        int nc = c + 2;
        if (nc < NCH) {
            int s2 = nc % NSTG;
            if (nc >= NSTG)
                MBARRIER_WAIT_PARITY_RELAXED(mb_free + s2 * 8, ((nc - NSTG) / NSTG) & 1);
            load_chunk(nc);
            CPASYNC_MBAR_ARRIVE(mb_full + s2 * 8);
        } else if (nc == NCH) {
            prefetch_l2(resb);
            prefetch_l2(resb + 32);
        }
    }

    // epilogue: bias + relu + residual
    const float* Abase = dir ? g_h1 : g_h0;
    float*       Cbase = dir ? g_h0 : g_h1;
    __half*      Chb   = dir ? g_ta0 : g_ta1;
    int mb0 = mbase + wm * 64, nb0 = nbase + wn * 32;
#pragma unroll
    for (int mf = 0; mf < 4; mf++) {
#pragma unroll
        for (int half = 0; half < 2; half++) {
            int row = mb0 + mf * 16 + half * 8 + g;
            const float* Ar = Abase + (size_t)row * HID + nb0;
            float* Cr = Cbase + (size_t)row * HID + nb0;
            __half* Chr = Chb + (size_t)row * HID + nb0;
#pragma unroll
            for (int nf = 0; nf < 4; nf++) {
                int cl = nf * 8 + 2 * t;
                float2 res = *(const float2*)(Ar + cl);
                float b0 = sbias[wn * 32 + cl];
                float b1 = sbias[wn * 32 + cl + 1];
                float v0 = acc[mf][nf][half * 2 + 0];
                float v1 = acc[mf][nf][half * 2 + 1];
                float2 o;
                o.x = res.x + fmaxf(v0 + b0, 0.0f);
                o.y = res.y + fmaxf(v1 + b1, 0.0f);
                *(float2*)(Cr + cl) = o;
                *(__half2*)(Chr + cl) = __floats2half2_rn(o.x, o.y);
            }
        }
    }

    // publish this tile (release)
    __syncthreads();
    if (tid == 0) {
        __threadfence();
        atomicAdd(&g_flags[l * MBLKS + mblk], 1);
    }
}

// ============================================================
// Kernel 5: LayerNorm + head (N=4). One warp per row. Reads exact fp32.
// ============================================================
__global__ void __launch_bounds__(256) head_kernel(const float* __restrict__ lng,
                                                   const float* __restrict__ lnb,
                                                   const float* __restrict__ hW,
                                                   const float* __restrict__ hb,
                                                   float* __restrict__ out) {
    int w = threadIdx.x >> 5, lane = threadIdx.x & 31;
    int row = blockIdx.x * 8 + w;
    const float4* h4 = (const float4*)(g_h0 + (size_t)row * HID);
    float4 v[16];
    float s = 0.f, ss = 0.f;
#pragma unroll
    for (int i = 0; i < 16; i++) {
        v[i] = h4[i * 32 + lane];
        s += v[i].x + v[i].y + v[i].z + v[i].w;
        ss += v[i].x * v[i].x + v[i].y * v[i].y + v[i].z * v[i].z + v[i].w * v[i].w;
    }
#pragma unroll
    for (int off = 16; off; off >>= 1) {
        s += __shfl_xor_sync(0xffffffffu, s, off);
        ss += __shfl_xor_sync(0xffffffffu, ss, off);
    }
    float mu = s * (1.0f / HID);
    float var = ss * (1.0f / HID) - mu * mu;
    float rs = rsqrtf(var + 1e-5f);
    float a0 = 0.f, a1 = 0.f, a2 = 0.f, a3 = 0.f;
    const float4* g4 = (const float4*)lng;
    const float4* b4 = (const float4*)lnb;
    const float4* w4 = (const float4*)hW;
#pragma unroll 1
    for (int i = 0; i < 16; i++) {
        int k4 = i * 32 + lane;
        float4 gg = g4[k4], bb = b4[k4];
        float hn[4];
        hn[0] = (v[i].x - mu) * rs * gg.x + bb.x;
        hn[1] = (v[i].y - mu) * rs * gg.y + bb.y;
        hn[2] = (v[i].z - mu) * rs * gg.z + bb.z;
        hn[3] = (v[i].w - mu) * rs * gg.w + bb.w;
#pragma unroll
        for (int j = 0; j < 4; j++) {
            float4 wr = w4[k4 * 4 + j];
            a0 += hn[j] * wr.x;
            a1 += hn[j] * wr.y;
            a2 += hn[j] * wr.z;
            a3 += hn[j] * wr.w;
        }
    }
#pragma unroll
    for (int off = 16; off; off >>= 1) {
        a0 += __shfl_xor_sync(0xffffffffu, a0, off);
        a1 += __shfl_xor_sync(0xffffffffu, a1, off);
        a2 += __shfl_xor_sync(0xffffffffu, a2, off);
        a3 += __shfl_xor_sync(0xffffffffu, a3, off);
    }
    if (lane == 0) {
        float4 hbv = *(const float4*)hb;
        float4 o;
        o.x = a0 + hbv.x; o.y = a1 + hbv.y; o.z = a2 + hbv.z; o.w = a3 + hbv.w;
        ((float4*)out)[row] = o;
    }
}

// ============================================================
extern "C" void kernel_launch(void* const* d_in, const int* in_sizes, int n_in,
                              void* d_out, int out_size) {
    const float* x   = (const float*)d_in[0];
    const float* eW  = (const float*)d_in[1];
    const float* eb  = (const float*)d_in[2];
    const float* lW  = (const float*)d_in[3];
    const float* lb  = (const float*)d_in[4];
    const float* lng = (const float*)d_in[5];
    const float* lnb = (const float*)d_in[6];
    const float* hW  = (const float*)d_in[7];
    const float* hb  = (const float*)d_in[8];

    cudaFuncSetAttribute(gemm_all_kernel, cudaFuncAttributeMaxDynamicSharedMemorySize, DYNSMEM);

    zero_flags_kernel<<<(NLAYER * MBLKS + 255) / 256, 256>>>();
    patch_kernel<<<BATCH / 8, 256>>>(x);
    wtrans_kernel<<<dim3(HID / 32, HID / 32, NLAYER), dim3(32, 8)>>>(lW);
    embed_kernel<<<dim3(HID / 128, BATCH / 64), 256>>>(eW, eb);
    gemm_all_kernel<<<NLAYER * MBLKS * NBLKS, NTHR, DYNSMEM>>>(lb);
    head_kernel<<<BATCH / 8, 256>>>(lng, lnb, hW, hb, (float*)d_out);
}

// round 16
// speedup vs baseline: 1.3636x; 1.0012x over previous
#include <cuda_runtime.h>
#include <cuda_fp16.h>
#include <cstdint>
#include <cstddef>

#define BATCH   16384
#define HID     2048
#define NLAYER  8
#define PIN     25

#define MT      128
#define NT      128
#define KC      64                  // 64 fp16 k-values = 128B per row
#define NCH     (HID / KC)          // 32
#define NSTG    3
#define ABYTES  (MT * 128)          // 16384
#define BBYTES  (NT * 128)          // 16384
#define STGB    (ABYTES + BBYTES)   // 32768
#define DYNSMEM (NSTG * STGB + 1024) // 99328  (x2 CTAs = 194.5KB/SM)
#define NTHR    256
#define MBLKS   (BATCH / MT)        // 128
#define NBLKS   (HID / NT)          // 16

// ---------------- device scratch (allocation-free) ----------------
__device__ float  g_h0[(size_t)BATCH * HID];     // exact fp32 activations
__device__ float  g_h1[(size_t)BATCH * HID];
__device__ __half g_ta0[(size_t)BATCH * HID];    // fp16-rounded MMA copies
__device__ __half g_ta1[(size_t)BATCH * HID];
__device__ __half g_wt[(size_t)NLAYER * HID * HID];  // W^T fp16 [l][n][k]
__device__ float  g_patch[(size_t)BATCH * PIN];
__device__ int    g_flags[NLAYER * MBLKS];       // n-tiles done per (layer, m-block)

// ---------------- helpers ----------------
__device__ __forceinline__ uint32_t smem_u32(const void* p) {
    uint32_t a;
    asm("{ .reg .u64 t; cvta.to.shared.u64 t, %1; cvt.u32.u64 %0, t; }" : "=r"(a) : "l"(p));
    return a;
}

__device__ __forceinline__ void cp_async16(uint32_t s, const void* g) {
    asm volatile("cp.async.cg.shared.global [%0], [%1], 16;" :: "r"(s), "l"(g) : "memory");
}

__device__ __forceinline__ void prefetch_l2(const void* g) {
    asm volatile("prefetch.global.L2 [%0];" :: "l"(g));
}

__device__ __forceinline__ void mma_f16(float* c, const uint32_t* a, const uint32_t* b) {
    asm volatile(
        "mma.sync.aligned.m16n8k16.row.col.f32.f16.f16.f32 "
        "{%0,%1,%2,%3}, {%4,%5,%6,%7}, {%8,%9}, {%0,%1,%2,%3};"
        : "+f"(c[0]), "+f"(c[1]), "+f"(c[2]), "+f"(c[3])
        : "r"(a[0]), "r"(a[1]), "r"(a[2]), "r"(a[3]), "r"(b[0]), "r"(b[1]));
}

#define LDSM4(r0, r1, r2, r3, addr) \
    asm volatile("ldmatrix.sync.aligned.m8n8.x4.shared.b16 {%0,%1,%2,%3}, [%4];" \
        : "=r"(r0), "=r"(r1), "=r"(r2), "=r"(r3) : "r"(addr))

#define MBARRIER_INIT(addr, count) \
    asm volatile("mbarrier.init.shared.b64 [%0], %1;" \
        :: "r"((uint32_t)(addr)), "r"((uint32_t)(count)) : "memory")

#define MBARRIER_ARRIVE(addr) \
    asm volatile("mbarrier.arrive.shared.b64 _, [%0];" \
        :: "r"((uint32_t)(addr)) : "memory")

#define CPASYNC_MBAR_ARRIVE(addr) \
    asm volatile("cp.async.mbarrier.arrive.noinc.shared.b64 [%0];" \
        :: "r"((uint32_t)(addr)) : "memory")

#define MBARRIER_WAIT_PARITY(mbar_smem_addr, phase_parity) do { \
    uint32_t _mbar = (uint32_t)(mbar_smem_addr); \
    uint32_t _parity = (uint32_t)(phase_parity); \
    uint32_t _done; \
    asm volatile( \
        "{\n\t.reg .pred p;\n\t" \
        "mbarrier.try_wait.parity.acquire.cta.shared::cta.b64 p, [%1], %2;\n\t" \
        "selp.b32 %0, 1, 0, p;\n\t}" \
        : "=r"(_done) : "r"(_mbar), "r"(_parity) : "memory"); \
    if (!_done) { \
        asm volatile( \
            "{\n\t.reg .pred P1;\n\t" \
            "WAIT_LOOP_%=:\n\t" \
            "mbarrier.try_wait.parity.acquire.cta.shared::cta.b64 P1, [%0], %1, 0x989680;\n\t" \
            "@P1 bra.uni WAIT_DONE_%=;\n\t" \
            "bra.uni WAIT_LOOP_%=;\n\t" \
            "WAIT_DONE_%=:\n\t}" \
            :: "r"(_mbar), "r"(_parity) : "memory"); \
    } \
} while (0)

// producer-side wait: post-wait accesses are cp.async only (async proxy) -> relaxed
#define MBARRIER_WAIT_PARITY_RELAXED(mbar_smem_addr, phase_parity) do { \
    uint32_t _mbar = (uint32_t)(mbar_smem_addr); \
    uint32_t _parity = (uint32_t)(phase_parity); \
    uint32_t _done; \
    asm volatile( \
        "{\n\t.reg .pred p;\n\t" \
        "mbarrier.try_wait.parity.relaxed.cta.shared::cta.b64 p, [%1], %2, 0x989680;\n\t" \
        "selp.b32 %0, 1, 0, p;\n\t}" \
        : "=r"(_done) : "r"(_mbar), "r"(_parity) : "memory"); \
    if (!_done) { \
        asm volatile( \
            "{\n\t.reg .pred P1;\n\t" \
            "WAIT_LOOP_%=:\n\t" \
            "mbarrier.try_wait.parity.relaxed.cta.shared::cta.b64 P1, [%0], %1, 0x989680;\n\t" \
            "@P1 bra.uni WAIT_DONE_%=;\n\t" \
            "bra.uni WAIT_LOOP_%=;\n\t" \
            "WAIT_DONE_%=:\n\t}" \
            :: "r"(_mbar), "r"(_parity) : "memory"); \
    } \
} while (0)

// ============================================================
// Kernel 1: find agent, extract 5x5 patch (pad -1). Block 0 also
// zeroes the cross-layer flags (kernel completes before gemm launch).
// ============================================================
__global__ void __launch_bounds__(256) patch_kernel(const float* __restrict__ x) {
    if (blockIdx.x == 0) {
        for (int i = threadIdx.x; i < NLAYER * MBLKS; i += 256)
            g_flags[i] = 0;
    }
    int w = threadIdx.x >> 5, lane = threadIdx.x & 31;
    int b = blockIdx.x * 8 + w;
    const float* xb = x + (size_t)b * 1024;
    int found = 0;
#pragma unroll
    for (int s = 0; s < 32; s++)
        if (xb[s * 32 + lane] == 3.0f) found = s * 32 + lane;
#pragma unroll
    for (int off = 16; off; off >>= 1)
        found = max(found, __shfl_xor_sync(0xffffffffu, found, off));
    int row = found >> 5, col = found & 31;
    if (lane < PIN) {
        int r = row + lane / 5 - 2;
        int c = col + lane % 5 - 2;
        float v = (r < 0 || r > 31 || c < 0 || c > 31) ? -1.0f : xb[r * 32 + c];
        g_patch[(size_t)b * PIN + lane] = v;
    }
}

// ============================================================
// Kernel 2: transpose W[l][k][n] -> g_wt[l][n][k] as fp16 (RN)
// ============================================================
__global__ void wtrans_kernel(const float* __restrict__ Wall) {
    __shared__ float t[32][33];
    const float* W = Wall + (size_t)blockIdx.z * HID * HID;
    __half* WT = g_wt + (size_t)blockIdx.z * HID * HID;
    int n0 = blockIdx.x * 32, k0 = blockIdx.y * 32;
    int tx = threadIdx.x, ty = threadIdx.y;
#pragma unroll
    for (int i = 0; i < 4; i++)
        t[ty + i * 8][tx] = W[(size_t)(k0 + ty + i * 8) * HID + n0 + tx];
    __syncthreads();
#pragma unroll
    for (int i = 0; i < 4; i++)
        WT[(size_t)(n0 + ty + i * 8) * HID + k0 + tx] = __float2half_rn(t[tx][ty + i * 8]);
}

// ============================================================
// Kernel 3: embed  h0 = patch . embed_W + embed_b  (K=25).
// 4 cols x 4 rows per thread, CTA = 32 rows x 128 cols (8192 blocks for
// latency hiding). Broadcast LDS feeds 4-col FMAs; float4/half2 stores.
// Same per-element k order -> bit-identical results.
// ============================================================
__global__ void __launch_bounds__(256) embed_kernel(const float* __restrict__ eW,
                                                    const float* __restrict__ eb) {
    __shared__ float sp[32][PIN];
    int mb = blockIdx.y * 32, nb = blockIdx.x * 128;
    for (int i = threadIdx.x; i < 32 * PIN; i += 256)
        sp[i / PIN][i % PIN] = g_patch[(size_t)(mb + i / PIN) * PIN + i % PIN];
    __syncthreads();

    int tc = threadIdx.x & 31;          // 32 col-groups of 4 cols
    int sg = threadIdx.x >> 5;          // 8 row-groups of 4 rows (uniform per warp)
    int col = nb + tc * 4;

    float4 bv = *(const float4*)(eb + col);
    float acc[4][4];
#pragma unroll
    for (int s = 0; s < 4; s++) {
        acc[s][0] = bv.x; acc[s][1] = bv.y; acc[s][2] = bv.z; acc[s][3] = bv.w;
    }

    for (int k = 0; k < PIN; k++) {
        float4 w = *(const float4*)(eW + (size_t)k * HID + col);
#pragma unroll
        for (int s = 0; s < 4; s++) {
            float a = sp[sg * 4 + s][k];      // warp-broadcast
            acc[s][0] += a * w.x;
            acc[s][1] += a * w.y;
            acc[s][2] += a * w.z;
            acc[s][3] += a * w.w;
        }
    }

#pragma unroll
    for (int s = 0; s < 4; s++) {
        int row = mb + sg * 4 + s;
        float* h = g_h0 + (size_t)row * HID + col;
        __half* th = g_ta0 + (size_t)row * HID + col;
        *(float4*)h = make_float4(acc[s][0], acc[s][1], acc[s][2], acc[s][3]);
        *(__half2*)(th)     = __floats2half2_rn(acc[s][0], acc[s][1]);
        *(__half2*)(th + 2) = __floats2half2_rn(acc[s][2], acc[s][3]);
    }
}

// ============================================================
// Kernel 4: ALL residual layers fused:  C = A + relu(A @ W_l + b_l)
// grid = NLAYER * MBLKS * NBLKS; bid -> (l, m, n). Cross-layer dependency
// via g_flags[l-1][m]. Inner loop identical to R13/R14/R15.
// ============================================================
__global__ void __launch_bounds__(NTHR, 2) gemm_all_kernel(const float* __restrict__ bias_all) {
    int bid = blockIdx.x;
    int l = bid >> 11;                       // 2048 tiles per layer
    int r = bid & 2047;
    int mblk = r >> 4, nblk = r & 15;
    int dir = l & 1;
    const float* bias = bias_all + (size_t)l * HID;

    const __half* __restrict__ Ah = dir ? g_ta1 : g_ta0;
    const __half* __restrict__ W  = g_wt + (size_t)l * HID * HID;

    extern __shared__ char dynsmem[];
    uint32_t raw = smem_u32(dynsmem);
    uint32_t sbase = (raw + 1023u) & ~1023u;

    __shared__ float sbias[NT];
    __shared__ __align__(8) unsigned long long mbars[2 * NSTG];  // full[0..2], free[0..2]

    int tid = threadIdx.x;
    int mbase = mblk * MT, nbase = nblk * NT;
    if (tid < NT) sbias[tid] = bias[nbase + tid];

    uint32_t mb_full = smem_u32(&mbars[0]);
    uint32_t mb_free = smem_u32(&mbars[NSTG]);
    if (tid == 0) {
#pragma unroll
        for (int s = 0; s < NSTG; s++) {
            MBARRIER_INIT(mb_full + s * 8, NTHR);
            MBARRIER_INIT(mb_free + s * 8, 8);
        }
    }

    // cross-layer dependency: wait for all 16 n-tiles of (l-1, mblk)
    if (l > 0) {
        if (tid == 0) {
            int* f = &g_flags[(l - 1) * MBLKS + mblk];
            while (atomicAdd(f, 0) < NBLKS) __nanosleep(64);
            __threadfence();                 // acquire
        }
    }
    __syncthreads();   // mbars + sbias + dependency visible

    int wid = tid >> 5, lane = tid & 31;
    int wm = wid & 1, wn = wid >> 1;          // 2 m-warps x 4 n-warps
    int g = lane >> 2, t = lane & 3;

    int rl  = lane & 7;
    int sec = lane >> 3;
    int hi_a = sec >> 1;
    int r8_a = sec & 1;
    int hi_b = sec & 1;
    int nfo_b = sec >> 1;

    uint32_t rowbase_a[4];
#pragma unroll
    for (int mf = 0; mf < 4; mf++)
        rowbase_a[mf] = (uint32_t)(wm * 64 + mf * 16 + r8_a * 8 + rl) * 128;
    uint32_t rowbase_b[2];
#pragma unroll
    for (int p = 0; p < 2; p++)
        rowbase_b[p] = (uint32_t)ABYTES
                     + (uint32_t)(wn * 32 + (2 * p + nfo_b) * 8 + rl) * 128;

    int lrow = tid >> 3, lcid = tid & 7;
    uint32_t aSmOff = (uint32_t)(lrow * 128 + ((lcid ^ (lrow & 7)) * 16));
    uint32_t bSmOff = (uint32_t)ABYTES + aSmOff;
    const __half* aG = Ah + (size_t)(mbase + lrow) * HID + lcid * 8;
    const __half* bG = W  + (size_t)(nbase + lrow) * HID + lcid * 8;

    const float* resb = (dir ? g_h1 : g_h0)
                      + (size_t)(mbase + (tid >> 1)) * HID + nbase + (tid & 1) * 64;

    auto load_chunk = [&](int c) {
        uint32_t sa = sbase + (uint32_t)(c % NSTG) * STGB;
        const __half* a = aG + c * KC;
        const __half* b = bG + c * KC;
#pragma unroll
        for (int i = 0; i < 4; i++) {
            cp_async16(sa + aSmOff + i * 4096, a + (size_t)i * 32 * HID);
            cp_async16(sa + bSmOff + i * 4096, b + (size_t)i * 32 * HID);
        }
    };

    float acc[4][4][4];
#pragma unroll
    for (int i = 0; i < 4; i++)
#pragma unroll
        for (int j = 0; j < 4; j++)
#pragma unroll
            for (int q = 0; q < 4; q++) acc[i][j][q] = 0.0f;

    uint32_t fa[2][4];
    uint32_t fb[2][8];

    auto ldfa = [&](uint32_t stb, int ks, int mf, int slot) {
        uint32_t offa = (uint32_t)((((2 * ks) | hi_a) ^ rl) * 16);
        LDSM4(fa[slot][0], fa[slot][1], fa[slot][2], fa[slot][3],
              stb + rowbase_a[mf] + offa);
    };
    auto ldfb = [&](uint32_t stb, int ks, int slot) {
        uint32_t offb = (uint32_t)((((2 * ks) | hi_b) ^ rl) * 16);
        LDSM4(fb[slot][0], fb[slot][1], fb[slot][2], fb[slot][3],
              stb + rowbase_b[0] + offb);
        LDSM4(fb[slot][4], fb[slot][5], fb[slot][6], fb[slot][7],
              stb + rowbase_b[1] + offb);
    };

    load_chunk(0);
    CPASYNC_MBAR_ARRIVE(mb_full + 0 * 8);
    load_chunk(1);
    CPASYNC_MBAR_ARRIVE(mb_full + 1 * 8);
    MBARRIER_WAIT_PARITY(mb_full + 0 * 8, 0);
    ldfa(sbase, 0, 0, 0);
    ldfb(sbase, 0, 0);

    for (int c = 0; c < NCH; c++) {
        int s = c % NSTG;
        uint32_t stb = sbase + (uint32_t)s * STGB;
        int s1 = (c + 1) % NSTG;
        uint32_t stb1 = sbase + (uint32_t)s1 * STGB;
        int p1 = ((c + 1) / NSTG) & 1;
        bool more = (c + 1 < NCH);

#pragma unroll
        for (int ks = 0; ks < 4; ks++) {
            int fbc = ks & 1;
            if (ks == 3 && more)
                MBARRIER_WAIT_PARITY(mb_full + s1 * 8, p1);
#pragma unroll
            for (int mf = 0; mf < 4; mf++) {
                int step = ks * 4 + mf;
                int p = step & 1;
                if (mf == 2) {
                    if (ks < 3) ldfb(stb, ks + 1, fbc ^ 1);
                    else if (more) ldfb(stb1, 0, 0);
                }
                if (step < 15)
                    ldfa(stb, (step + 1) >> 2, (step + 1) & 3, p ^ 1);
                else if (more)
                    ldfa(stb1, 0, 0, 0);
#pragma unroll
                for (int nf = 0; nf < 4; nf++)
                    mma_f16(acc[mf][nf], fa[p], &fb[fbc][nf * 2]);
            }
        }
        if (lane == 0) MBARRIER_ARRIVE(mb_free + s * 8);

        int nc = c + 2;
        if (nc < NCH) {
            int s2 = nc % NSTG;
            if (nc >= NSTG)
                MBARRIER_WAIT_PARITY_RELAXED(mb_free + s2 * 8, ((nc - NSTG) / NSTG) & 1);
            load_chunk(nc);
            CPASYNC_MBAR_ARRIVE(mb_full + s2 * 8);
        } else if (nc == NCH) {
            prefetch_l2(resb);
            prefetch_l2(resb + 32);
        }
    }

    // epilogue: bias + relu + residual
    const float* Abase = dir ? g_h1 : g_h0;
    float*       Cbase = dir ? g_h0 : g_h1;
    __half*      Chb   = dir ? g_ta0 : g_ta1;
    int mb0 = mbase + wm * 64, nb0 = nbase + wn * 32;
#pragma unroll
    for (int mf = 0; mf < 4; mf++) {
#pragma unroll
        for (int half = 0; half < 2; half++) {
            int row = mb0 + mf * 16 + half * 8 + g;
            const float* Ar = Abase + (size_t)row * HID + nb0;
            float* Cr = Cbase + (size_t)row * HID + nb0;
            __half* Chr = Chb + (size_t)row * HID + nb0;
#pragma unroll
            for (int nf = 0; nf < 4; nf++) {
                int cl = nf * 8 + 2 * t;
                float2 res = *(const float2*)(Ar + cl);
                float b0 = sbias[wn * 32 + cl];
                float b1 = sbias[wn * 32 + cl + 1];
                float v0 = acc[mf][nf][half * 2 + 0];
                float v1 = acc[mf][nf][half * 2 + 1];
                float2 o;
                o.x = res.x + fmaxf(v0 + b0, 0.0f);
                o.y = res.y + fmaxf(v1 + b1, 0.0f);
                *(float2*)(Cr + cl) = o;
                *(__half2*)(Chr + cl) = __floats2half2_rn(o.x, o.y);
            }
        }
    }

    // publish this tile (release)
    __syncthreads();
    if (tid == 0) {
        __threadfence();
        atomicAdd(&g_flags[l * MBLKS + mblk], 1);
    }
}

// ============================================================
// Kernel 5: LayerNorm + head (N=4). One warp per row. Reads exact fp32.
// ============================================================
__global__ void __launch_bounds__(256) head_kernel(const float* __restrict__ lng,
                                                   const float* __restrict__ lnb,
                                                   const float* __restrict__ hW,
                                                   const float* __restrict__ hb,
                                                   float* __restrict__ out) {
    int w = threadIdx.x >> 5, lane = threadIdx.x & 31;
    int row = blockIdx.x * 8 + w;
    const float4* h4 = (const float4*)(g_h0 + (size_t)row * HID);
    float4 v[16];
    float s = 0.f, ss = 0.f;
#pragma unroll
    for (int i = 0; i < 16; i++) {
        v[i] = h4[i * 32 + lane];
        s += v[i].x + v[i].y + v[i].z + v[i].w;
        ss += v[i].x * v[i].x + v[i].y * v[i].y + v[i].z * v[i].z + v[i].w * v[i].w;
    }
#pragma unroll
    for (int off = 16; off; off >>= 1) {
        s += __shfl_xor_sync(0xffffffffu, s, off);
        ss += __shfl_xor_sync(0xffffffffu, ss, off);
    }
    float mu = s * (1.0f / HID);
    float var = ss * (1.0f / HID) - mu * mu;
    float rs = rsqrtf(var + 1e-5f);
    float a0 = 0.f, a1 = 0.f, a2 = 0.f, a3 = 0.f;
    const float4* g4 = (const float4*)lng;
    const float4* b4 = (const float4*)lnb;
    const float4* w4 = (const float4*)hW;
#pragma unroll 1
    for (int i = 0; i < 16; i++) {
        int k4 = i * 32 + lane;
        float4 gg = g4[k4], bb = b4[k4];
        float hn[4];
        hn[0] = (v[i].x - mu) * rs * gg.x + bb.x;
        hn[1] = (v[i].y - mu) * rs * gg.y + bb.y;
        hn[2] = (v[i].z - mu) * rs * gg.z + bb.z;
        hn[3] = (v[i].w - mu) * rs * gg.w + bb.w;
#pragma unroll
        for (int j = 0; j < 4; j++) {
            float4 wr = w4[k4 * 4 + j];
            a0 += hn[j] * wr.x;
            a1 += hn[j] * wr.y;
            a2 += hn[j] * wr.z;
            a3 += hn[j] * wr.w;
        }
    }
#pragma unroll
    for (int off = 16; off; off >>= 1) {
        a0 += __shfl_xor_sync(0xffffffffu, a0, off);
        a1 += __shfl_xor_sync(0xffffffffu, a1, off);
        a2 += __shfl_xor_sync(0xffffffffu, a2, off);
        a3 += __shfl_xor_sync(0xffffffffu, a3, off);
    }
    if (lane == 0) {
        float4 hbv = *(const float4*)hb;
        float4 o;
        o.x = a0 + hbv.x; o.y = a1 + hbv.y; o.z = a2 + hbv.z; o.w = a3 + hbv.w;
        ((float4*)out)[row] = o;
    }
}

// ============================================================
extern "C" void kernel_launch(void* const* d_in, const int* in_sizes, int n_in,
                              void* d_out, int out_size) {
    const float* x   = (const float*)d_in[0];
    const float* eW  = (const float*)d_in[1];
    const float* eb  = (const float*)d_in[2];
    const float* lW  = (const float*)d_in[3];
    const float* lb  = (const float*)d_in[4];
    const float* lng = (const float*)d_in[5];
    const float* lnb = (const float*)d_in[6];
    const float* hW  = (const float*)d_in[7];
    const float* hb  = (const float*)d_in[8];

    cudaFuncSetAttribute(gemm_all_kernel, cudaFuncAttributeMaxDynamicSharedMemorySize, DYNSMEM);

    patch_kernel<<<BATCH / 8, 256>>>(x);
    wtrans_kernel<<<dim3(HID / 32, HID / 32, NLAYER), dim3(32, 8)>>>(lW);
    embed_kernel<<<dim3(HID / 128, BATCH / 32), 256>>>(eW, eb);
    gemm_all_kernel<<<NLAYER * MBLKS * NBLKS, NTHR, DYNSMEM>>>(lb);
    head_kernel<<<BATCH / 8, 256>>>(lng, lnb, hW, hb, (float*)d_out);
}